// round 2
// baseline (speedup 1.0000x reference)
#include <cuda_runtime.h>
#include <cstdint>

// Problem constants (fixed by the reference)
#define MAX_NODES 100000
#define IN_DIM   128
#define HID_DIM  128
#define OUT_DIM  64

// ---------------- scratch (no allocs allowed -> device globals) -------------
__device__ float g_bufA[MAX_NODES * 128];   // h1 / x1
__device__ float g_bufB[MAX_NODES * 128];   // agg1 / h2
__device__ float g_onorm[MAX_NODES];
__device__ float g_inorm[MAX_NODES];

// ---------------- small helpers --------------------------------------------
__global__ void k_zero_norms(int n) {
    int i = blockIdx.x * blockDim.x + threadIdx.x;
    if (i < n) { g_onorm[i] = 0.f; g_inorm[i] = 0.f; }
}

__global__ void k_deg(const int* __restrict__ src, const int* __restrict__ dst, int nE) {
    int e = blockIdx.x * blockDim.x + threadIdx.x;
    if (e < nE) {
        atomicAdd(&g_onorm[src[e]], 1.f);
        atomicAdd(&g_inorm[dst[e]], 1.f);
    }
}

__global__ void k_norm(int n) {
    int i = blockIdx.x * blockDim.x + threadIdx.x;
    if (i < n) {
        g_onorm[i] = rsqrtf(fmaxf(g_onorm[i], 1.f));
        g_inorm[i] = rsqrtf(fmaxf(g_inorm[i], 1.f));
    }
}

__global__ void k_zero_buf(float* __restrict__ p, int n4) {
    int i = blockIdx.x * blockDim.x + threadIdx.x;
    if (i < n4) ((float4*)p)[i] = make_float4(0.f, 0.f, 0.f, 0.f);
}

// ---------------- GEMM: Y[M,N] = (X[M,128] * onorm[M]) @ W[128,N] -----------
// K is always 128. W fully resident in smem; X tile stored transposed
// (k-major) so the compute loop reads Xs with warp-broadcast addresses.
template<int N, int BM>
__global__ __launch_bounds__(256)
void k_gemm(const float* __restrict__ X, const float* __restrict__ W,
            float* __restrict__ Y, int M)
{
    extern __shared__ float sm[];
    float* Ws = sm;                    // [128][N]   (16B-aligned base)
    float* Xs = sm + 128 * N;          // [128][BM+1] (scalar access only)
    constexpr int XST = BM + 1;

    const int tid  = threadIdx.x;
    const int row0 = blockIdx.x * BM;

    // load W (row-major [k][n]) as float4s
    for (int i = tid; i < 32 * N; i += 256)
        ((float4*)Ws)[i] = ((const float4*)W)[i];

    // load X tile, scaled by out_norm, transposed into Xs[k][r]
    for (int i = tid; i < BM * 32; i += 256) {
        int r  = i >> 5;
        int k4 = (i & 31) * 4;
        int gr = row0 + r;
        float4 v = make_float4(0.f, 0.f, 0.f, 0.f);
        float sc = 0.f;
        if (gr < M) {
            v  = ((const float4*)(X + (size_t)gr * 128))[k4 >> 2];
            sc = g_onorm[gr];
        }
        Xs[(k4 + 0) * XST + r] = v.x * sc;
        Xs[(k4 + 1) * XST + r] = v.y * sc;
        Xs[(k4 + 2) * XST + r] = v.z * sc;
        Xs[(k4 + 3) * XST + r] = v.w * sc;
    }
    __syncthreads();

    constexpr int CT = N / 4;              // col groups per row-group
    const int ct = tid % CT;               // this thread's 4-col group
    const int rt = tid / CT;               // this thread's 8-row group

    float acc[8][4] = {};
    const float* xp = Xs + rt * 8;
    const float* wp = Ws + ct * 4;

    #pragma unroll 4
    for (int k = 0; k < 128; k++) {
        float4 b = *(const float4*)(wp + k * N);
        const float* xr = xp + k * XST;
        #pragma unroll
        for (int r = 0; r < 8; r++) {
            float a = xr[r];
            acc[r][0] += a * b.x;
            acc[r][1] += a * b.y;
            acc[r][2] += a * b.z;
            acc[r][3] += a * b.w;
        }
    }

    #pragma unroll
    for (int r = 0; r < 8; r++) {
        int gr = row0 + rt * 8 + r;
        if (gr < M) {
            ((float4*)(Y + (size_t)gr * N))[ct] =
                make_float4(acc[r][0], acc[r][1], acc[r][2], acc[r][3]);
        }
    }
}

// ---------------- edge scatter: agg[dst] += h[src] --------------------------
__device__ __forceinline__ void red_v4(float4* p, float4 v) {
    asm volatile("red.global.add.v4.f32 [%0], {%1,%2,%3,%4};"
                 :: "l"(p), "f"(v.x), "f"(v.y), "f"(v.z), "f"(v.w)
                 : "memory");
}

// D=128: one warp per edge, each lane one float4
__global__ void k_scat128(const int* __restrict__ src, const int* __restrict__ dst,
                          const float* __restrict__ h, float* __restrict__ agg, int nE)
{
    int gid  = blockIdx.x * blockDim.x + threadIdx.x;
    int e    = gid >> 5;
    int lane = gid & 31;
    if (e >= nE) return;
    int sn = src[e], dn = dst[e];
    float4 v = ((const float4*)h)[(size_t)sn * 32 + lane];
    red_v4(((float4*)agg) + (size_t)dn * 32 + lane, v);
}

// D=64: half warp per edge
__global__ void k_scat64(const int* __restrict__ src, const int* __restrict__ dst,
                         const float* __restrict__ h, float* __restrict__ agg, int nE)
{
    int gid = blockIdx.x * blockDim.x + threadIdx.x;
    int e   = gid >> 4;
    int sub = gid & 15;
    if (e >= nE) return;
    int sn = src[e], dn = dst[e];
    float4 v = ((const float4*)h)[(size_t)sn * 16 + sub];
    red_v4(((float4*)agg) + (size_t)dn * 16 + sub, v);
}

// ---------------- epilogues -------------------------------------------------
// x1 = relu(agg * in_norm + b1)  (D=128)
__global__ void k_relu_bias(const float* __restrict__ agg, const float* __restrict__ b1,
                            float* __restrict__ out, int M)
{
    int i = blockIdx.x * blockDim.x + threadIdx.x;   // float4 index
    if (i >= M * 32) return;
    int node = i >> 5;
    int c4   = (i & 31) * 4;
    float nn = g_inorm[node];
    float4 a = ((const float4*)agg)[i];
    float4 r;
    r.x = fmaxf(fmaf(a.x, nn, b1[c4 + 0]), 0.f);
    r.y = fmaxf(fmaf(a.y, nn, b1[c4 + 1]), 0.f);
    r.z = fmaxf(fmaf(a.z, nn, b1[c4 + 2]), 0.f);
    r.w = fmaxf(fmaf(a.w, nn, b1[c4 + 3]), 0.f);
    ((float4*)out)[i] = r;
}

// out = out * in_norm + b2  (D=64, in place on d_out)
__global__ void k_final(float* __restrict__ out, const float* __restrict__ b2, int M)
{
    int i = blockIdx.x * blockDim.x + threadIdx.x;   // float4 index
    if (i >= M * 16) return;
    int node = i >> 4;
    int c4   = (i & 15) * 4;
    float nn = g_inorm[node];
    float4 a = ((float4*)out)[i];
    a.x = fmaf(a.x, nn, b2[c4 + 0]);
    a.y = fmaf(a.y, nn, b2[c4 + 1]);
    a.z = fmaf(a.z, nn, b2[c4 + 2]);
    a.w = fmaf(a.w, nn, b2[c4 + 3]);
    ((float4*)out)[i] = a;
}

// ---------------- launch ----------------------------------------------------
extern "C" void kernel_launch(void* const* d_in, const int* in_sizes, int n_in,
                              void* d_out, int out_size)
{
    const float* feat = (const float*)d_in[0];
    const int*   src  = (const int*)  d_in[1];
    const int*   dst  = (const int*)  d_in[2];
    const float* W1   = (const float*)d_in[3];
    const float* b1   = (const float*)d_in[4];
    const float* W2   = (const float*)d_in[5];
    const float* b2   = (const float*)d_in[6];
    float* out = (float*)d_out;

    const int M  = in_sizes[0] / IN_DIM;   // 100000
    const int nE = in_sizes[1];            // 1600000

    float *pA = nullptr, *pB = nullptr;
    cudaGetSymbolAddress((void**)&pA, g_bufA);
    cudaGetSymbolAddress((void**)&pB, g_bufB);

    constexpr int SMEM1 = (128 * 128 + 128 * (64 + 1)) * 4;   // 98816
    constexpr int SMEM2 = (128 * 64 + 128 * (128 + 1)) * 4;   // 98816
    cudaFuncSetAttribute(k_gemm<128, 64>,  cudaFuncAttributeMaxDynamicSharedMemorySize, SMEM1);
    cudaFuncSetAttribute(k_gemm<64, 128>,  cudaFuncAttributeMaxDynamicSharedMemorySize, SMEM2);

    // 1) degrees + norms
    k_zero_norms<<<(M + 255) / 256, 256>>>(M);
    k_deg<<<(nE + 255) / 256, 256>>>(src, dst, nE);
    k_norm<<<(M + 255) / 256, 256>>>(M);

    // 2) layer 1: h1 = (feat * onorm) @ W1
    k_gemm<128, 64><<<(M + 63) / 64, 256, SMEM1>>>(feat, W1, pA, M);
    k_zero_buf<<<(M * 32 + 255) / 256, 256>>>(pB, M * 32);
    k_scat128<<<((size_t)nE * 32 + 255) / 256, 256>>>(src, dst, pA, pB, nE);
    k_relu_bias<<<(M * 32 + 255) / 256, 256>>>(pB, b1, pA, M);

    // 3) layer 2: h2 = (x1 * onorm) @ W2
    k_gemm<64, 128><<<(M + 127) / 128, 256, SMEM2>>>(pA, W2, pB, M);
    k_zero_buf<<<(M * 16 + 255) / 256, 256>>>(out, M * 16);
    k_scat64<<<((size_t)nE * 16 + 255) / 256, 256>>>(src, dst, pB, out, nE);
    k_final<<<(M * 16 + 255) / 256, 256>>>(out, b2, M);
}

// round 3
// speedup vs baseline: 1.1166x; 1.1166x over previous
#include <cuda_runtime.h>
#include <cstdint>

#define MAX_NODES 100000
#define MAX_EDGES 1700000
#define IN_DIM   128
#define HID_DIM  128
#define OUT_DIM  64

// ---------------- scratch (no allocs allowed -> device globals) -------------
__device__ float g_bufA[MAX_NODES * 128];   // h1 / h2
__device__ float g_bufB[MAX_NODES * 128];   // x1
__device__ float g_onorm[MAX_NODES];
__device__ float g_inorm[MAX_NODES];
__device__ int   g_indeg[MAX_NODES];
__device__ int   g_outdeg[MAX_NODES];
__device__ int   g_off[MAX_NODES + 1];
__device__ int   g_cur[MAX_NODES];
__device__ int   g_esrc[MAX_EDGES];

// ---------------- degree / CSR build ---------------------------------------
__global__ void k_zero_counts(int n) {
    int i = blockIdx.x * blockDim.x + threadIdx.x;
    if (i < n) { g_indeg[i] = 0; g_outdeg[i] = 0; }
}

__global__ void k_count(const int* __restrict__ src, const int* __restrict__ dst, int nE) {
    int e = blockIdx.x * blockDim.x + threadIdx.x;
    if (e < nE) {
        atomicAdd(&g_indeg[dst[e]], 1);
        atomicAdd(&g_outdeg[src[e]], 1);
    }
}

__global__ void k_norm(int n) {
    int i = blockIdx.x * blockDim.x + threadIdx.x;
    if (i < n) {
        g_onorm[i] = rsqrtf(fmaxf((float)g_outdeg[i], 1.f));
        g_inorm[i] = rsqrtf(fmaxf((float)g_indeg[i],  1.f));
    }
}

// single-block exclusive scan of g_indeg -> g_off / g_cur
__global__ void k_scan(int n, int nE) {
    __shared__ int sm[1024];
    const int t = threadIdx.x;
    const int chunk = (n + 1023) >> 10;
    const int beg = t * chunk;
    const int end = min(n, beg + chunk);

    int s = 0;
    for (int i = beg; i < end; i++) s += g_indeg[i];
    sm[t] = s;
    __syncthreads();
    for (int d = 1; d < 1024; d <<= 1) {
        int v = (t >= d) ? sm[t - d] : 0;
        __syncthreads();
        sm[t] += v;
        __syncthreads();
    }
    int run = sm[t] - s;          // exclusive base
    for (int i = beg; i < end; i++) {
        g_off[i] = run;
        g_cur[i] = run;
        run += g_indeg[i];
    }
    if (t == 1023) g_off[n] = nE;
}

__global__ void k_fill(const int* __restrict__ src, const int* __restrict__ dst, int nE) {
    int e = blockIdx.x * blockDim.x + threadIdx.x;
    if (e < nE) {
        int slot = atomicAdd(&g_cur[dst[e]], 1);
        g_esrc[slot] = src[e];
    }
}

// ---------------- GEMM: Y[M,N] = (X[M,128] * onorm[M]) @ W[128,N] -----------
template<int N, int BM>
__global__ __launch_bounds__(256)
void k_gemm(const float* __restrict__ X, const float* __restrict__ W,
            float* __restrict__ Y, int M)
{
    extern __shared__ float sm[];
    float* Ws = sm;                    // [128][N]
    float* Xs = sm + 128 * N;          // [128][BM+1]
    constexpr int XST = BM + 1;

    const int tid  = threadIdx.x;
    const int row0 = blockIdx.x * BM;

    for (int i = tid; i < 32 * N; i += 256)
        ((float4*)Ws)[i] = ((const float4*)W)[i];

    for (int i = tid; i < BM * 32; i += 256) {
        int r  = i >> 5;
        int k4 = (i & 31) * 4;
        int gr = row0 + r;
        float4 v = make_float4(0.f, 0.f, 0.f, 0.f);
        float sc = 0.f;
        if (gr < M) {
            v  = ((const float4*)(X + (size_t)gr * 128))[k4 >> 2];
            sc = g_onorm[gr];
        }
        Xs[(k4 + 0) * XST + r] = v.x * sc;
        Xs[(k4 + 1) * XST + r] = v.y * sc;
        Xs[(k4 + 2) * XST + r] = v.z * sc;
        Xs[(k4 + 3) * XST + r] = v.w * sc;
    }
    __syncthreads();

    constexpr int CT = N / 4;
    const int ct = tid % CT;
    const int rt = tid / CT;

    float acc[8][4] = {};
    const float* xp = Xs + rt * 8;
    const float* wp = Ws + ct * 4;

    #pragma unroll 4
    for (int k = 0; k < 128; k++) {
        float4 b = *(const float4*)(wp + k * N);
        const float* xr = xp + k * XST;
        #pragma unroll
        for (int r = 0; r < 8; r++) {
            float a = xr[r];
            acc[r][0] += a * b.x;
            acc[r][1] += a * b.y;
            acc[r][2] += a * b.z;
            acc[r][3] += a * b.w;
        }
    }

    #pragma unroll
    for (int r = 0; r < 8; r++) {
        int gr = row0 + rt * 8 + r;
        if (gr < M) {
            ((float4*)(Y + (size_t)gr * N))[ct] =
                make_float4(acc[r][0], acc[r][1], acc[r][2], acc[r][3]);
        }
    }
}

// ---------------- CSR gather (no atomics) -----------------------------------
// D=128: one warp per dst node. x1 = relu(sum_{e in(d)} h[src_e] * inorm + b1)
__global__ __launch_bounds__(256)
void k_gather128(const float* __restrict__ h, const float* __restrict__ b1,
                 float* __restrict__ out, int M)
{
    int gid  = blockIdx.x * blockDim.x + threadIdx.x;
    int node = gid >> 5;
    int lane = gid & 31;
    if (node >= M) return;

    const int beg = g_off[node];
    const int end = g_off[node + 1];

    float4 acc = make_float4(0.f, 0.f, 0.f, 0.f);
    const float4* h4 = (const float4*)h;

    int j = beg;
    for (; j + 4 <= end; j += 4) {
        int s0 = g_esrc[j + 0];
        int s1 = g_esrc[j + 1];
        int s2 = g_esrc[j + 2];
        int s3 = g_esrc[j + 3];
        float4 v0 = h4[(size_t)s0 * 32 + lane];
        float4 v1 = h4[(size_t)s1 * 32 + lane];
        float4 v2 = h4[(size_t)s2 * 32 + lane];
        float4 v3 = h4[(size_t)s3 * 32 + lane];
        acc.x += v0.x + v1.x + v2.x + v3.x;
        acc.y += v0.y + v1.y + v2.y + v3.y;
        acc.z += v0.z + v1.z + v2.z + v3.z;
        acc.w += v0.w + v1.w + v2.w + v3.w;
    }
    for (; j < end; j++) {
        int s = g_esrc[j];
        float4 v = h4[(size_t)s * 32 + lane];
        acc.x += v.x; acc.y += v.y; acc.z += v.z; acc.w += v.w;
    }

    float nn = g_inorm[node];
    float4 bb = ((const float4*)b1)[lane];
    float4 r;
    r.x = fmaxf(fmaf(acc.x, nn, bb.x), 0.f);
    r.y = fmaxf(fmaf(acc.y, nn, bb.y), 0.f);
    r.z = fmaxf(fmaf(acc.z, nn, bb.z), 0.f);
    r.w = fmaxf(fmaf(acc.w, nn, bb.w), 0.f);
    ((float4*)out)[(size_t)node * 32 + lane] = r;
}

// D=64: half warp per dst node. out = sum h2[src_e] * inorm + b2
__global__ __launch_bounds__(256)
void k_gather64(const float* __restrict__ h, const float* __restrict__ b2,
                float* __restrict__ out, int M)
{
    int gid  = blockIdx.x * blockDim.x + threadIdx.x;
    int node = gid >> 4;
    int sub  = gid & 15;
    if (node >= M) return;

    const int beg = g_off[node];
    const int end = g_off[node + 1];

    float4 acc = make_float4(0.f, 0.f, 0.f, 0.f);
    const float4* h4 = (const float4*)h;

    int j = beg;
    for (; j + 4 <= end; j += 4) {
        int s0 = g_esrc[j + 0];
        int s1 = g_esrc[j + 1];
        int s2 = g_esrc[j + 2];
        int s3 = g_esrc[j + 3];
        float4 v0 = h4[(size_t)s0 * 16 + sub];
        float4 v1 = h4[(size_t)s1 * 16 + sub];
        float4 v2 = h4[(size_t)s2 * 16 + sub];
        float4 v3 = h4[(size_t)s3 * 16 + sub];
        acc.x += v0.x + v1.x + v2.x + v3.x;
        acc.y += v0.y + v1.y + v2.y + v3.y;
        acc.z += v0.z + v1.z + v2.z + v3.z;
        acc.w += v0.w + v1.w + v2.w + v3.w;
    }
    for (; j < end; j++) {
        int s = g_esrc[j];
        float4 v = h4[(size_t)s * 16 + sub];
        acc.x += v.x; acc.y += v.y; acc.z += v.z; acc.w += v.w;
    }

    float nn = g_inorm[node];
    float4 bb = ((const float4*)b2)[sub];
    float4 r;
    r.x = fmaf(acc.x, nn, bb.x);
    r.y = fmaf(acc.y, nn, bb.y);
    r.z = fmaf(acc.z, nn, bb.z);
    r.w = fmaf(acc.w, nn, bb.w);
    ((float4*)out)[(size_t)node * 16 + sub] = r;
}

// ---------------- launch ----------------------------------------------------
extern "C" void kernel_launch(void* const* d_in, const int* in_sizes, int n_in,
                              void* d_out, int out_size)
{
    const float* feat = (const float*)d_in[0];
    const int*   src  = (const int*)  d_in[1];
    const int*   dst  = (const int*)  d_in[2];
    const float* W1   = (const float*)d_in[3];
    const float* b1   = (const float*)d_in[4];
    const float* W2   = (const float*)d_in[5];
    const float* b2   = (const float*)d_in[6];
    float* out = (float*)d_out;

    const int M  = in_sizes[0] / IN_DIM;   // 100000
    const int nE = in_sizes[1];            // 1600000

    float *pA = nullptr, *pB = nullptr;
    cudaGetSymbolAddress((void**)&pA, g_bufA);
    cudaGetSymbolAddress((void**)&pB, g_bufB);

    constexpr int SMEM1 = (128 * 128 + 128 * (64 + 1)) * 4;
    constexpr int SMEM2 = (128 * 64 + 128 * (128 + 1)) * 4;
    cudaFuncSetAttribute(k_gemm<128, 64>,  cudaFuncAttributeMaxDynamicSharedMemorySize, SMEM1);
    cudaFuncSetAttribute(k_gemm<64, 128>,  cudaFuncAttributeMaxDynamicSharedMemorySize, SMEM2);

    // 1) degrees + CSR build
    k_zero_counts<<<(M + 255) / 256, 256>>>(M);
    k_count<<<(nE + 255) / 256, 256>>>(src, dst, nE);
    k_norm<<<(M + 255) / 256, 256>>>(M);
    k_scan<<<1, 1024>>>(M, nE);
    k_fill<<<(nE + 255) / 256, 256>>>(src, dst, nE);

    // 2) layer 1: h1 = (feat * onorm) @ W1 ; x1 = relu(gather(h1)*inorm + b1)
    k_gemm<128, 64><<<(M + 63) / 64, 256, SMEM1>>>(feat, W1, pA, M);
    k_gather128<<<((size_t)M * 32 + 255) / 256, 256>>>(pA, b1, pB, M);

    // 3) layer 2: h2 = (x1 * onorm) @ W2 ; out = gather(h2)*inorm + b2
    k_gemm<64, 128><<<(M + 127) / 128, 256, SMEM2>>>(pB, W2, pA, M);
    k_gather64<<<((size_t)M * 16 + 255) / 256, 256>>>(pA, b2, out, M);
}

// round 4
// speedup vs baseline: 1.7536x; 1.5705x over previous
#include <cuda_runtime.h>
#include <cstdint>

#define MAX_NODES 100000
#define MAX_EDGES 1700000
#define IN_DIM   128
#define HID_DIM  128
#define OUT_DIM  64

// ---------------- scratch (no allocs allowed -> device globals) -------------
__device__ float g_bufA[MAX_NODES * 128];   // h1 / h2
__device__ float g_bufB[MAX_NODES * 128];   // x1
__device__ float g_onorm[MAX_NODES];
__device__ float g_inorm[MAX_NODES];
__device__ int   g_indeg[MAX_NODES];
__device__ int   g_outdeg[MAX_NODES];
__device__ int   g_off[MAX_NODES + 1];
__device__ int   g_cur[MAX_NODES];
__device__ int   g_esrc[MAX_EDGES];
__device__ int   g_bsum[256];
__device__ int   g_bbase[256];

// ---------------- degree / CSR build ---------------------------------------
__global__ void k_zero_counts(int n) {
    int i = blockIdx.x * blockDim.x + threadIdx.x;
    if (i < n) { g_indeg[i] = 0; g_outdeg[i] = 0; }
}

__global__ void k_count(const int* __restrict__ src, const int* __restrict__ dst, int nE) {
    int e = blockIdx.x * blockDim.x + threadIdx.x;
    if (e < nE) {
        atomicAdd(&g_indeg[dst[e]], 1);
        atomicAdd(&g_outdeg[src[e]], 1);
    }
}

__global__ void k_norm(int n) {
    int i = blockIdx.x * blockDim.x + threadIdx.x;
    if (i < n) {
        g_onorm[i] = rsqrtf(fmaxf((float)g_outdeg[i], 1.f));
        g_inorm[i] = rsqrtf(fmaxf((float)g_indeg[i],  1.f));
    }
}

// hierarchical exclusive scan of g_indeg -> g_off / g_cur
// stage 1: per-block (1024 elems) exclusive scan, block totals to g_bsum
__global__ void k_scan1(int n) {
    __shared__ int sm[1024];
    int t = threadIdx.x;
    int i = blockIdx.x * 1024 + t;
    int v = (i < n) ? g_indeg[i] : 0;
    sm[t] = v;
    __syncthreads();
    #pragma unroll
    for (int d = 1; d < 1024; d <<= 1) {
        int u = (t >= d) ? sm[t - d] : 0;
        __syncthreads();
        sm[t] += u;
        __syncthreads();
    }
    if (i < n) g_off[i] = sm[t] - v;           // exclusive within block
    if (t == 1023) g_bsum[blockIdx.x] = sm[1023];
}

// stage 2: single block scans the (<=256) block sums
__global__ void k_scan2(int nb) {
    __shared__ int sm[256];
    int t = threadIdx.x;
    int v = (t < nb) ? g_bsum[t] : 0;
    sm[t] = v;
    __syncthreads();
    #pragma unroll
    for (int d = 1; d < 256; d <<= 1) {
        int u = (t >= d) ? sm[t - d] : 0;
        __syncthreads();
        sm[t] += u;
        __syncthreads();
    }
    if (t < nb) g_bbase[t] = sm[t] - v;        // exclusive block base
}

// stage 3: add block base, init cursors, close the offset array
__global__ void k_scan3(int n, int nE) {
    int i = blockIdx.x * blockDim.x + threadIdx.x;
    if (i < n) {
        int o = g_off[i] + g_bbase[i >> 10];
        g_off[i] = o;
        g_cur[i] = o;
    }
    if (i == 0) g_off[n] = nE;
}

__global__ void k_fill(const int* __restrict__ src, const int* __restrict__ dst, int nE) {
    int e = blockIdx.x * blockDim.x + threadIdx.x;
    if (e < nE) {
        int slot = atomicAdd(&g_cur[dst[e]], 1);
        g_esrc[slot] = src[e];
    }
}

// ---------------- packed f32x2 helpers --------------------------------------
typedef unsigned long long u64;

__device__ __forceinline__ u64 pack2(float lo, float hi) {
    u64 r;
    asm("mov.b64 %0, {%1, %2};" : "=l"(r) : "f"(lo), "f"(hi));
    return r;
}
__device__ __forceinline__ void unpack2(u64 p, float& lo, float& hi) {
    asm("mov.b64 {%0, %1}, %2;" : "=f"(lo), "=f"(hi) : "l"(p));
}
__device__ __forceinline__ void fma2(u64& d, u64 a, u64 b) {
    asm("fma.rn.f32x2 %0, %1, %2, %0;" : "+l"(d) : "l"(a), "l"(b));
}

// ---------------- GEMM: Y[M,N] = (X[M,128] * onorm[M]) @ W[128,N] -----------
// K=128. W resident in smem row-major [k][n]; X tile transposed [k][r] with
// stride BM+2 (keeps 8B alignment so row-pairs load as ld.shared.b64).
// Each thread: 8 rows (4 row-pairs) x 4 cols, accumulated in f32x2 pairs.
template<int N, int BM>
__global__ __launch_bounds__(256)
void k_gemm(const float* __restrict__ X, const float* __restrict__ W,
            float* __restrict__ Y, int M)
{
    extern __shared__ float sm[];
    float* Ws = sm;                    // [128][N]
    float* Xs = sm + 128 * N;          // [128][BM+2]
    constexpr int XST = BM + 2;

    const int tid  = threadIdx.x;
    const int row0 = blockIdx.x * BM;

    for (int i = tid; i < 32 * N; i += 256)
        ((float4*)Ws)[i] = ((const float4*)W)[i];

    for (int i = tid; i < BM * 32; i += 256) {
        int r  = i >> 5;
        int k4 = (i & 31) * 4;
        int gr = row0 + r;
        float4 v = make_float4(0.f, 0.f, 0.f, 0.f);
        float sc = 0.f;
        if (gr < M) {
            v  = ((const float4*)(X + (size_t)gr * 128))[k4 >> 2];
            sc = g_onorm[gr];
        }
        Xs[(k4 + 0) * XST + r] = v.x * sc;
        Xs[(k4 + 1) * XST + r] = v.y * sc;
        Xs[(k4 + 2) * XST + r] = v.z * sc;
        Xs[(k4 + 3) * XST + r] = v.w * sc;
    }
    __syncthreads();

    constexpr int CT = N / 4;
    const int ct = tid % CT;               // 4-col group
    const int rt = tid / CT;               // 8-row group

    u64 acc2[4][4];                        // [row-pair][col], lo=even row
    #pragma unroll
    for (int p = 0; p < 4; p++)
        #pragma unroll
        for (int c = 0; c < 4; c++) acc2[p][c] = 0ull;

    const float* xp = Xs + rt * 8;
    const float* wp = Ws + ct * 4;

    #pragma unroll 4
    for (int k = 0; k < 128; k++) {
        const float* xr = xp + k * XST;
        u64 a0 = *(const u64*)(xr + 0);
        u64 a1 = *(const u64*)(xr + 2);
        u64 a2 = *(const u64*)(xr + 4);
        u64 a3 = *(const u64*)(xr + 6);
        float4 b = *(const float4*)(wp + k * N);
        u64 bx = pack2(b.x, b.x);
        u64 by = pack2(b.y, b.y);
        u64 bz = pack2(b.z, b.z);
        u64 bw = pack2(b.w, b.w);
        fma2(acc2[0][0], a0, bx); fma2(acc2[0][1], a0, by);
        fma2(acc2[0][2], a0, bz); fma2(acc2[0][3], a0, bw);
        fma2(acc2[1][0], a1, bx); fma2(acc2[1][1], a1, by);
        fma2(acc2[1][2], a1, bz); fma2(acc2[1][3], a1, bw);
        fma2(acc2[2][0], a2, bx); fma2(acc2[2][1], a2, by);
        fma2(acc2[2][2], a2, bz); fma2(acc2[2][3], a2, bw);
        fma2(acc2[3][0], a3, bx); fma2(acc2[3][1], a3, by);
        fma2(acc2[3][2], a3, bz); fma2(acc2[3][3], a3, bw);
    }

    #pragma unroll
    for (int p = 0; p < 4; p++) {
        float4 lo, hi;
        unpack2(acc2[p][0], lo.x, hi.x);
        unpack2(acc2[p][1], lo.y, hi.y);
        unpack2(acc2[p][2], lo.z, hi.z);
        unpack2(acc2[p][3], lo.w, hi.w);
        int gr = row0 + rt * 8 + 2 * p;
        if (gr < M)     ((float4*)(Y + (size_t)gr * N))[ct] = lo;
        if (gr + 1 < M) ((float4*)(Y + (size_t)(gr + 1) * N))[ct] = hi;
    }
}

// ---------------- CSR gather (no atomics) -----------------------------------
__global__ __launch_bounds__(256)
void k_gather128(const float* __restrict__ h, const float* __restrict__ b1,
                 float* __restrict__ out, int M)
{
    int gid  = blockIdx.x * blockDim.x + threadIdx.x;
    int node = gid >> 5;
    int lane = gid & 31;
    if (node >= M) return;

    const int beg = g_off[node];
    const int end = g_off[node + 1];

    float4 acc = make_float4(0.f, 0.f, 0.f, 0.f);
    const float4* h4 = (const float4*)h;

    int j = beg;
    for (; j + 4 <= end; j += 4) {
        int s0 = g_esrc[j + 0];
        int s1 = g_esrc[j + 1];
        int s2 = g_esrc[j + 2];
        int s3 = g_esrc[j + 3];
        float4 v0 = h4[(size_t)s0 * 32 + lane];
        float4 v1 = h4[(size_t)s1 * 32 + lane];
        float4 v2 = h4[(size_t)s2 * 32 + lane];
        float4 v3 = h4[(size_t)s3 * 32 + lane];
        acc.x += v0.x + v1.x + v2.x + v3.x;
        acc.y += v0.y + v1.y + v2.y + v3.y;
        acc.z += v0.z + v1.z + v2.z + v3.z;
        acc.w += v0.w + v1.w + v2.w + v3.w;
    }
    for (; j < end; j++) {
        int s = g_esrc[j];
        float4 v = h4[(size_t)s * 32 + lane];
        acc.x += v.x; acc.y += v.y; acc.z += v.z; acc.w += v.w;
    }

    float nn = g_inorm[node];
    float4 bb = ((const float4*)b1)[lane];
    float4 r;
    r.x = fmaxf(fmaf(acc.x, nn, bb.x), 0.f);
    r.y = fmaxf(fmaf(acc.y, nn, bb.y), 0.f);
    r.z = fmaxf(fmaf(acc.z, nn, bb.z), 0.f);
    r.w = fmaxf(fmaf(acc.w, nn, bb.w), 0.f);
    ((float4*)out)[(size_t)node * 32 + lane] = r;
}

__global__ __launch_bounds__(256)
void k_gather64(const float* __restrict__ h, const float* __restrict__ b2,
                float* __restrict__ out, int M)
{
    int gid  = blockIdx.x * blockDim.x + threadIdx.x;
    int node = gid >> 4;
    int sub  = gid & 15;
    if (node >= M) return;

    const int beg = g_off[node];
    const int end = g_off[node + 1];

    float4 acc = make_float4(0.f, 0.f, 0.f, 0.f);
    const float4* h4 = (const float4*)h;

    int j = beg;
    for (; j + 4 <= end; j += 4) {
        int s0 = g_esrc[j + 0];
        int s1 = g_esrc[j + 1];
        int s2 = g_esrc[j + 2];
        int s3 = g_esrc[j + 3];
        float4 v0 = h4[(size_t)s0 * 16 + sub];
        float4 v1 = h4[(size_t)s1 * 16 + sub];
        float4 v2 = h4[(size_t)s2 * 16 + sub];
        float4 v3 = h4[(size_t)s3 * 16 + sub];
        acc.x += v0.x + v1.x + v2.x + v3.x;
        acc.y += v0.y + v1.y + v2.y + v3.y;
        acc.z += v0.z + v1.z + v2.z + v3.z;
        acc.w += v0.w + v1.w + v2.w + v3.w;
    }
    for (; j < end; j++) {
        int s = g_esrc[j];
        float4 v = h4[(size_t)s * 16 + sub];
        acc.x += v.x; acc.y += v.y; acc.z += v.z; acc.w += v.w;
    }

    float nn = g_inorm[node];
    float4 bb = ((const float4*)b2)[sub];
    float4 r;
    r.x = fmaf(acc.x, nn, bb.x);
    r.y = fmaf(acc.y, nn, bb.y);
    r.z = fmaf(acc.z, nn, bb.z);
    r.w = fmaf(acc.w, nn, bb.w);
    ((float4*)out)[(size_t)node * 16 + sub] = r;
}

// ---------------- launch ----------------------------------------------------
extern "C" void kernel_launch(void* const* d_in, const int* in_sizes, int n_in,
                              void* d_out, int out_size)
{
    const float* feat = (const float*)d_in[0];
    const int*   src  = (const int*)  d_in[1];
    const int*   dst  = (const int*)  d_in[2];
    const float* W1   = (const float*)d_in[3];
    const float* b1   = (const float*)d_in[4];
    const float* W2   = (const float*)d_in[5];
    const float* b2   = (const float*)d_in[6];
    float* out = (float*)d_out;

    const int M  = in_sizes[0] / IN_DIM;   // 100000
    const int nE = in_sizes[1];            // 1600000

    float *pA = nullptr, *pB = nullptr;
    cudaGetSymbolAddress((void**)&pA, g_bufA);
    cudaGetSymbolAddress((void**)&pB, g_bufB);

    constexpr int SMEM1 = (128 * 128 + 128 * (64 + 2)) * 4;    // 99328
    constexpr int SMEM2 = (128 * 64 + 128 * (128 + 2)) * 4;    // 99328
    cudaFuncSetAttribute(k_gemm<128, 64>,  cudaFuncAttributeMaxDynamicSharedMemorySize, SMEM1);
    cudaFuncSetAttribute(k_gemm<64, 128>,  cudaFuncAttributeMaxDynamicSharedMemorySize, SMEM2);

    const int nb = (M + 1023) >> 10;       // 98 scan blocks

    // 1) degrees + CSR build
    k_zero_counts<<<(M + 255) / 256, 256>>>(M);
    k_count<<<(nE + 255) / 256, 256>>>(src, dst, nE);
    k_norm<<<(M + 255) / 256, 256>>>(M);
    k_scan1<<<nb, 1024>>>(M);
    k_scan2<<<1, 256>>>(nb);
    k_scan3<<<(M + 255) / 256, 256>>>(M, nE);
    k_fill<<<(nE + 255) / 256, 256>>>(src, dst, nE);

    // 2) layer 1
    k_gemm<128, 64><<<(M + 63) / 64, 256, SMEM1>>>(feat, W1, pA, M);
    k_gather128<<<((size_t)M * 32 + 255) / 256, 256>>>(pA, b1, pB, M);

    // 3) layer 2
    k_gemm<64, 128><<<(M + 127) / 128, 256, SMEM2>>>(pB, W2, pA, M);
    k_gather64<<<((size_t)M * 16 + 255) / 256, 256>>>(pA, b2, out, M);
}

// round 5
// speedup vs baseline: 1.8847x; 1.0748x over previous
#include <cuda_runtime.h>
#include <cstdint>

#define MAX_NODES 100000
#define MAX_EDGES 1700000
#define IN_DIM   128
#define HID_DIM  128
#define OUT_DIM  64

// ---------------- scratch (no allocs allowed -> device globals) -------------
__device__ float g_bufA[MAX_NODES * 128];   // h1 / h2
__device__ float g_bufB[MAX_NODES * 128];   // x1
__device__ float g_onorm[MAX_NODES];
__device__ float g_inorm[MAX_NODES];
__device__ int   g_indeg[MAX_NODES];
__device__ int   g_outdeg[MAX_NODES];
__device__ int   g_off[MAX_NODES + 1];
__device__ int   g_cur[MAX_NODES];
__device__ int   g_esrc[MAX_EDGES];
__device__ int   g_bsum[256];
__device__ int   g_bbase[256];

// ---------------- degree / CSR build ---------------------------------------
__global__ void k_zero_counts(int n) {
    int i = blockIdx.x * blockDim.x + threadIdx.x;
    if (i < n) { g_indeg[i] = 0; g_outdeg[i] = 0; }
}

__global__ void k_count(const int* __restrict__ src, const int* __restrict__ dst, int nE) {
    int e = blockIdx.x * blockDim.x + threadIdx.x;
    if (e < nE) {
        atomicAdd(&g_indeg[dst[e]], 1);
        atomicAdd(&g_outdeg[src[e]], 1);
    }
}

__global__ void k_norm(int n) {
    int i = blockIdx.x * blockDim.x + threadIdx.x;
    if (i < n) {
        g_onorm[i] = rsqrtf(fmaxf((float)g_outdeg[i], 1.f));
        g_inorm[i] = rsqrtf(fmaxf((float)g_indeg[i],  1.f));
    }
}

// hierarchical exclusive scan of g_indeg -> g_off / g_cur
__global__ void k_scan1(int n) {
    __shared__ int sm[1024];
    int t = threadIdx.x;
    int i = blockIdx.x * 1024 + t;
    int v = (i < n) ? g_indeg[i] : 0;
    sm[t] = v;
    __syncthreads();
    #pragma unroll
    for (int d = 1; d < 1024; d <<= 1) {
        int u = (t >= d) ? sm[t - d] : 0;
        __syncthreads();
        sm[t] += u;
        __syncthreads();
    }
    if (i < n) g_off[i] = sm[t] - v;
    if (t == 1023) g_bsum[blockIdx.x] = sm[1023];
}

__global__ void k_scan2(int nb) {
    __shared__ int sm[256];
    int t = threadIdx.x;
    int v = (t < nb) ? g_bsum[t] : 0;
    sm[t] = v;
    __syncthreads();
    #pragma unroll
    for (int d = 1; d < 256; d <<= 1) {
        int u = (t >= d) ? sm[t - d] : 0;
        __syncthreads();
        sm[t] += u;
        __syncthreads();
    }
    if (t < nb) g_bbase[t] = sm[t] - v;
}

__global__ void k_scan3(int n, int nE) {
    int i = blockIdx.x * blockDim.x + threadIdx.x;
    if (i < n) {
        int o = g_off[i] + g_bbase[i >> 10];
        g_off[i] = o;
        g_cur[i] = o;
    }
    if (i == 0) g_off[n] = nE;
}

__global__ void k_fill(const int* __restrict__ src, const int* __restrict__ dst, int nE) {
    int e = blockIdx.x * blockDim.x + threadIdx.x;
    if (e < nE) {
        int slot = atomicAdd(&g_cur[dst[e]], 1);
        g_esrc[slot] = src[e];
    }
}

// ---------------- packed f32x2 helpers --------------------------------------
typedef unsigned long long u64;

__device__ __forceinline__ u64 pack2(float lo, float hi) {
    u64 r;
    asm("mov.b64 %0, {%1, %2};" : "=l"(r) : "f"(lo), "f"(hi));
    return r;
}
__device__ __forceinline__ void unpack2(u64 p, float& lo, float& hi) {
    asm("mov.b64 {%0, %1}, %2;" : "=f"(lo), "=f"(hi) : "l"(p));
}
__device__ __forceinline__ void fma2(u64& d, u64 a, u64 b) {
    asm("fma.rn.f32x2 %0, %1, %2, %0;" : "+l"(d) : "l"(a), "l"(b));
}

// ---------------- GEMM: Y[M,N] = (X[M,128] * onorm[M]) @ W[128,N] -----------
template<int N, int BM>
__global__ __launch_bounds__(256)
void k_gemm(const float* __restrict__ X, const float* __restrict__ W,
            float* __restrict__ Y, int M)
{
    extern __shared__ float sm[];
    float* Ws = sm;                    // [128][N]
    float* Xs = sm + 128 * N;          // [128][BM+2]
    constexpr int XST = BM + 2;

    const int tid  = threadIdx.x;
    const int row0 = blockIdx.x * BM;

    for (int i = tid; i < 32 * N; i += 256)
        ((float4*)Ws)[i] = ((const float4*)W)[i];

    for (int i = tid; i < BM * 32; i += 256) {
        int r  = i >> 5;
        int k4 = (i & 31) * 4;
        int gr = row0 + r;
        float4 v = make_float4(0.f, 0.f, 0.f, 0.f);
        float sc = 0.f;
        if (gr < M) {
            v  = ((const float4*)(X + (size_t)gr * 128))[k4 >> 2];
            sc = g_onorm[gr];
        }
        Xs[(k4 + 0) * XST + r] = v.x * sc;
        Xs[(k4 + 1) * XST + r] = v.y * sc;
        Xs[(k4 + 2) * XST + r] = v.z * sc;
        Xs[(k4 + 3) * XST + r] = v.w * sc;
    }
    __syncthreads();

    constexpr int CT = N / 4;
    const int ct = tid % CT;
    const int rt = tid / CT;

    u64 acc2[4][4];
    #pragma unroll
    for (int p = 0; p < 4; p++)
        #pragma unroll
        for (int c = 0; c < 4; c++) acc2[p][c] = 0ull;

    const float* xp = Xs + rt * 8;
    const float* wp = Ws + ct * 4;

    #pragma unroll 4
    for (int k = 0; k < 128; k++) {
        const float* xr = xp + k * XST;
        u64 a0 = *(const u64*)(xr + 0);
        u64 a1 = *(const u64*)(xr + 2);
        u64 a2 = *(const u64*)(xr + 4);
        u64 a3 = *(const u64*)(xr + 6);
        float4 b = *(const float4*)(wp + k * N);
        u64 bx = pack2(b.x, b.x);
        u64 by = pack2(b.y, b.y);
        u64 bz = pack2(b.z, b.z);
        u64 bw = pack2(b.w, b.w);
        fma2(acc2[0][0], a0, bx); fma2(acc2[0][1], a0, by);
        fma2(acc2[0][2], a0, bz); fma2(acc2[0][3], a0, bw);
        fma2(acc2[1][0], a1, bx); fma2(acc2[1][1], a1, by);
        fma2(acc2[1][2], a1, bz); fma2(acc2[1][3], a1, bw);
        fma2(acc2[2][0], a2, bx); fma2(acc2[2][1], a2, by);
        fma2(acc2[2][2], a2, bz); fma2(acc2[2][3], a2, bw);
        fma2(acc2[3][0], a3, bx); fma2(acc2[3][1], a3, by);
        fma2(acc2[3][2], a3, bz); fma2(acc2[3][3], a3, bw);
    }

    #pragma unroll
    for (int p = 0; p < 4; p++) {
        float4 lo, hi;
        unpack2(acc2[p][0], lo.x, hi.x);
        unpack2(acc2[p][1], lo.y, hi.y);
        unpack2(acc2[p][2], lo.z, hi.z);
        unpack2(acc2[p][3], lo.w, hi.w);
        int gr = row0 + rt * 8 + 2 * p;
        if (gr < M)     ((float4*)(Y + (size_t)gr * N))[ct] = lo;
        if (gr + 1 < M) ((float4*)(Y + (size_t)(gr + 1) * N))[ct] = hi;
    }
}

// ---------------- CSR gather (no atomics) -----------------------------------
// D=128: one warp per dst node, unroll 8 for deeper MLP.
__global__ __launch_bounds__(256)
void k_gather128(const float* __restrict__ h, const float* __restrict__ b1,
                 float* __restrict__ out, int M)
{
    int gid  = blockIdx.x * blockDim.x + threadIdx.x;
    int node = gid >> 5;
    int lane = gid & 31;
    if (node >= M) return;

    const int beg = g_off[node];
    const int end = g_off[node + 1];

    float4 acc = make_float4(0.f, 0.f, 0.f, 0.f);
    const float4* h4 = (const float4*)h;

    int j = beg;
    for (; j + 8 <= end; j += 8) {
        int s0 = g_esrc[j + 0], s1 = g_esrc[j + 1];
        int s2 = g_esrc[j + 2], s3 = g_esrc[j + 3];
        int s4 = g_esrc[j + 4], s5 = g_esrc[j + 5];
        int s6 = g_esrc[j + 6], s7 = g_esrc[j + 7];
        float4 v0 = h4[(size_t)s0 * 32 + lane];
        float4 v1 = h4[(size_t)s1 * 32 + lane];
        float4 v2 = h4[(size_t)s2 * 32 + lane];
        float4 v3 = h4[(size_t)s3 * 32 + lane];
        float4 v4 = h4[(size_t)s4 * 32 + lane];
        float4 v5 = h4[(size_t)s5 * 32 + lane];
        float4 v6 = h4[(size_t)s6 * 32 + lane];
        float4 v7 = h4[(size_t)s7 * 32 + lane];
        acc.x += (v0.x + v1.x) + (v2.x + v3.x) + ((v4.x + v5.x) + (v6.x + v7.x));
        acc.y += (v0.y + v1.y) + (v2.y + v3.y) + ((v4.y + v5.y) + (v6.y + v7.y));
        acc.z += (v0.z + v1.z) + (v2.z + v3.z) + ((v4.z + v5.z) + (v6.z + v7.z));
        acc.w += (v0.w + v1.w) + (v2.w + v3.w) + ((v4.w + v5.w) + (v6.w + v7.w));
    }
    for (; j + 2 <= end; j += 2) {
        int s0 = g_esrc[j + 0], s1 = g_esrc[j + 1];
        float4 v0 = h4[(size_t)s0 * 32 + lane];
        float4 v1 = h4[(size_t)s1 * 32 + lane];
        acc.x += v0.x + v1.x; acc.y += v0.y + v1.y;
        acc.z += v0.z + v1.z; acc.w += v0.w + v1.w;
    }
    if (j < end) {
        int s = g_esrc[j];
        float4 v = h4[(size_t)s * 32 + lane];
        acc.x += v.x; acc.y += v.y; acc.z += v.z; acc.w += v.w;
    }

    float nn = g_inorm[node];
    float4 bb = ((const float4*)b1)[lane];
    float4 r;
    r.x = fmaxf(fmaf(acc.x, nn, bb.x), 0.f);
    r.y = fmaxf(fmaf(acc.y, nn, bb.y), 0.f);
    r.z = fmaxf(fmaf(acc.z, nn, bb.z), 0.f);
    r.w = fmaxf(fmaf(acc.w, nn, bb.w), 0.f);
    ((float4*)out)[(size_t)node * 32 + lane] = r;
}

// D=64: half warp per dst node, unroll 8.
__global__ __launch_bounds__(256)
void k_gather64(const float* __restrict__ h, const float* __restrict__ b2,
                float* __restrict__ out, int M)
{
    int gid  = blockIdx.x * blockDim.x + threadIdx.x;
    int node = gid >> 4;
    int sub  = gid & 15;
    if (node >= M) return;

    const int beg = g_off[node];
    const int end = g_off[node + 1];

    float4 acc = make_float4(0.f, 0.f, 0.f, 0.f);
    const float4* h4 = (const float4*)h;

    int j = beg;
    for (; j + 8 <= end; j += 8) {
        int s0 = g_esrc[j + 0], s1 = g_esrc[j + 1];
        int s2 = g_esrc[j + 2], s3 = g_esrc[j + 3];
        int s4 = g_esrc[j + 4], s5 = g_esrc[j + 5];
        int s6 = g_esrc[j + 6], s7 = g_esrc[j + 7];
        float4 v0 = h4[(size_t)s0 * 16 + sub];
        float4 v1 = h4[(size_t)s1 * 16 + sub];
        float4 v2 = h4[(size_t)s2 * 16 + sub];
        float4 v3 = h4[(size_t)s3 * 16 + sub];
        float4 v4 = h4[(size_t)s4 * 16 + sub];
        float4 v5 = h4[(size_t)s5 * 16 + sub];
        float4 v6 = h4[(size_t)s6 * 16 + sub];
        float4 v7 = h4[(size_t)s7 * 16 + sub];
        acc.x += (v0.x + v1.x) + (v2.x + v3.x) + ((v4.x + v5.x) + (v6.x + v7.x));
        acc.y += (v0.y + v1.y) + (v2.y + v3.y) + ((v4.y + v5.y) + (v6.y + v7.y));
        acc.z += (v0.z + v1.z) + (v2.z + v3.z) + ((v4.z + v5.z) + (v6.z + v7.z));
        acc.w += (v0.w + v1.w) + (v2.w + v3.w) + ((v4.w + v5.w) + (v6.w + v7.w));
    }
    for (; j + 2 <= end; j += 2) {
        int s0 = g_esrc[j + 0], s1 = g_esrc[j + 1];
        float4 v0 = h4[(size_t)s0 * 16 + sub];
        float4 v1 = h4[(size_t)s1 * 16 + sub];
        acc.x += v0.x + v1.x; acc.y += v0.y + v1.y;
        acc.z += v0.z + v1.z; acc.w += v0.w + v1.w;
    }
    if (j < end) {
        int s = g_esrc[j];
        float4 v = h4[(size_t)s * 16 + sub];
        acc.x += v.x; acc.y += v.y; acc.z += v.z; acc.w += v.w;
    }

    float nn = g_inorm[node];
    float4 bb = ((const float4*)b2)[sub];
    float4 r;
    r.x = fmaf(acc.x, nn, bb.x);
    r.y = fmaf(acc.y, nn, bb.y);
    r.z = fmaf(acc.z, nn, bb.z);
    r.w = fmaf(acc.w, nn, bb.w);
    ((float4*)out)[(size_t)node * 16 + sub] = r;
}

// ---------------- launch ----------------------------------------------------
extern "C" void kernel_launch(void* const* d_in, const int* in_sizes, int n_in,
                              void* d_out, int out_size)
{
    const float* feat = (const float*)d_in[0];
    const int*   src  = (const int*)  d_in[1];
    const int*   dst  = (const int*)  d_in[2];
    const float* W1   = (const float*)d_in[3];
    const float* b1   = (const float*)d_in[4];
    const float* W2   = (const float*)d_in[5];
    const float* b2   = (const float*)d_in[6];
    float* out = (float*)d_out;

    const int M  = in_sizes[0] / IN_DIM;   // 100000
    const int nE = in_sizes[1];            // 1600000

    float *pA = nullptr, *pB = nullptr;
    cudaGetSymbolAddress((void**)&pA, g_bufA);
    cudaGetSymbolAddress((void**)&pB, g_bufB);

    constexpr int SMEM1 = (128 * 128 + 128 * (64 + 2)) * 4;
    constexpr int SMEM2 = (128 * 64 + 128 * (128 + 2)) * 4;
    cudaFuncSetAttribute(k_gemm<128, 64>,  cudaFuncAttributeMaxDynamicSharedMemorySize, SMEM1);
    cudaFuncSetAttribute(k_gemm<64, 128>,  cudaFuncAttributeMaxDynamicSharedMemorySize, SMEM2);

    // One-time side-stream / event creation (first call is the un-captured
    // correctness run; subsequent capture reuses them). Non-blocking is
    // mandatory: legacy-stream implicit sync would invalidate capture.
    static cudaStream_t s_side = nullptr;
    static cudaEvent_t  s_evFork = nullptr, s_evJoin = nullptr;
    if (!s_side) {
        cudaStreamCreateWithFlags(&s_side, cudaStreamNonBlocking);
        cudaEventCreateWithFlags(&s_evFork, cudaEventDisableTiming);
        cudaEventCreateWithFlags(&s_evJoin, cudaEventDisableTiming);
    }

    const int nb = (M + 1023) >> 10;

    // 1) degrees (both streams depend on this)
    k_zero_counts<<<(M + 255) / 256, 256>>>(M);
    k_count<<<(nE + 255) / 256, 256>>>(src, dst, nE);
    cudaEventRecord(s_evFork, 0);

    // side stream: CSR build (needs indeg only)
    cudaStreamWaitEvent(s_side, s_evFork, 0);
    k_scan1<<<nb, 1024, 0, s_side>>>(M);
    k_scan2<<<1, 256, 0, s_side>>>(nb);
    k_scan3<<<(M + 255) / 256, 256, 0, s_side>>>(M, nE);
    k_fill<<<(nE + 255) / 256, 256, 0, s_side>>>(src, dst, nE);
    cudaEventRecord(s_evJoin, s_side);

    // main stream: norms + gemm1 (needs onorm only)
    k_norm<<<(M + 255) / 256, 256>>>(M);
    k_gemm<128, 64><<<(M + 63) / 64, 256, SMEM1>>>(feat, W1, pA, M);

    // join: gather needs CSR + h1
    cudaStreamWaitEvent(0, s_evJoin, 0);
    k_gather128<<<((size_t)M * 32 + 255) / 256, 256>>>(pA, b1, pB, M);

    // layer 2
    k_gemm<64, 128><<<(M + 127) / 128, 256, SMEM2>>>(pB, W2, pA, M);
    k_gather64<<<((size_t)M * 16 + 255) / 256, 256>>>(pA, b2, out, M);
}

// round 7
// speedup vs baseline: 2.0742x; 1.1005x over previous
#include <cuda_runtime.h>
#include <cuda_fp16.h>
#include <cstdint>

#define MAX_NODES 100000
#define MAX_EDGES 1700000
#define IN_DIM   128
#define HID_DIM  128
#define OUT_DIM  64

// ---------------- scratch (no allocs allowed -> device globals) -------------
__device__ float g_bufA[MAX_NODES * 128];   // h1 / h2 (as __half), reinterpreted
__device__ float g_bufB[MAX_NODES * 128];   // x1 (fp32)
__device__ float g_onorm[MAX_NODES];
__device__ float g_inorm[MAX_NODES];
__device__ int   g_indeg[MAX_NODES];
__device__ int   g_outdeg[MAX_NODES];
__device__ int   g_off[MAX_NODES + 1];
__device__ int   g_cur[MAX_NODES];
__device__ int   g_esrc[MAX_EDGES];
__device__ int   g_bsum[256];
__device__ int   g_bbase[256];

// ---------------- bit casts --------------------------------------------------
__device__ __forceinline__ unsigned h2_as_u32(__half2 h) {
    return *reinterpret_cast<unsigned*>(&h);
}
__device__ __forceinline__ __half2 u32_as_h2(unsigned u) {
    return *reinterpret_cast<__half2*>(&u);
}

// ---------------- degree / CSR build ---------------------------------------
__global__ void k_zero_counts(int n) {
    int i = blockIdx.x * blockDim.x + threadIdx.x;
    if (i < n) { g_indeg[i] = 0; g_outdeg[i] = 0; }
}

__global__ void k_count(const int* __restrict__ src, const int* __restrict__ dst, int nE) {
    int e = blockIdx.x * blockDim.x + threadIdx.x;
    if (e < nE) {
        atomicAdd(&g_indeg[dst[e]], 1);
        atomicAdd(&g_outdeg[src[e]], 1);
    }
}

__global__ void k_norm(int n) {
    int i = blockIdx.x * blockDim.x + threadIdx.x;
    if (i < n) {
        g_onorm[i] = rsqrtf(fmaxf((float)g_outdeg[i], 1.f));
        g_inorm[i] = rsqrtf(fmaxf((float)g_indeg[i],  1.f));
    }
}

__global__ void k_scan1(int n) {
    __shared__ int sm[1024];
    int t = threadIdx.x;
    int i = blockIdx.x * 1024 + t;
    int v = (i < n) ? g_indeg[i] : 0;
    sm[t] = v;
    __syncthreads();
    #pragma unroll
    for (int d = 1; d < 1024; d <<= 1) {
        int u = (t >= d) ? sm[t - d] : 0;
        __syncthreads();
        sm[t] += u;
        __syncthreads();
    }
    if (i < n) g_off[i] = sm[t] - v;
    if (t == 1023) g_bsum[blockIdx.x] = sm[1023];
}

__global__ void k_scan2(int nb) {
    __shared__ int sm[256];
    int t = threadIdx.x;
    int v = (t < nb) ? g_bsum[t] : 0;
    sm[t] = v;
    __syncthreads();
    #pragma unroll
    for (int d = 1; d < 256; d <<= 1) {
        int u = (t >= d) ? sm[t - d] : 0;
        __syncthreads();
        sm[t] += u;
        __syncthreads();
    }
    if (t < nb) g_bbase[t] = sm[t] - v;
}

__global__ void k_scan3(int n, int nE) {
    int i = blockIdx.x * blockDim.x + threadIdx.x;
    if (i < n) {
        int o = g_off[i] + g_bbase[i >> 10];
        g_off[i] = o;
        g_cur[i] = o;
    }
    if (i == 0) g_off[n] = nE;
}

__global__ void k_fill(const int* __restrict__ src, const int* __restrict__ dst, int nE) {
    int e = blockIdx.x * blockDim.x + threadIdx.x;
    if (e < nE) {
        int slot = atomicAdd(&g_cur[dst[e]], 1);
        g_esrc[slot] = src[e];
    }
}

// ---------------- packed f32x2 helpers --------------------------------------
typedef unsigned long long u64;

__device__ __forceinline__ u64 pack2(float lo, float hi) {
    u64 r;
    asm("mov.b64 %0, {%1, %2};" : "=l"(r) : "f"(lo), "f"(hi));
    return r;
}
__device__ __forceinline__ void unpack2(u64 p, float& lo, float& hi) {
    asm("mov.b64 {%0, %1}, %2;" : "=f"(lo), "=f"(hi) : "l"(p));
}
__device__ __forceinline__ void fma2(u64& d, u64 a, u64 b) {
    asm("fma.rn.f32x2 %0, %1, %2, %0;" : "+l"(d) : "l"(a), "l"(b));
}

// ---------------- GEMM: Y = (X[M,128] * onorm) @ W[128,N], fp16 out --------
template<int N, int BM>
__global__ __launch_bounds__(256)
void k_gemm(const float* __restrict__ X, const float* __restrict__ W,
            __half* __restrict__ Y, int M)
{
    extern __shared__ float sm[];
    float* Ws = sm;                    // [128][N]
    float* Xs = sm + 128 * N;          // [128][BM+2]
    constexpr int XST = BM + 2;

    const int tid  = threadIdx.x;
    const int row0 = blockIdx.x * BM;

    for (int i = tid; i < 32 * N; i += 256)
        ((float4*)Ws)[i] = ((const float4*)W)[i];

    for (int i = tid; i < BM * 32; i += 256) {
        int r  = i >> 5;
        int k4 = (i & 31) * 4;
        int gr = row0 + r;
        float4 v = make_float4(0.f, 0.f, 0.f, 0.f);
        float sc = 0.f;
        if (gr < M) {
            v  = ((const float4*)(X + (size_t)gr * 128))[k4 >> 2];
            sc = g_onorm[gr];
        }
        Xs[(k4 + 0) * XST + r] = v.x * sc;
        Xs[(k4 + 1) * XST + r] = v.y * sc;
        Xs[(k4 + 2) * XST + r] = v.z * sc;
        Xs[(k4 + 3) * XST + r] = v.w * sc;
    }
    __syncthreads();

    constexpr int CT = N / 4;
    const int ct = tid % CT;
    const int rt = tid / CT;

    u64 acc2[4][4];
    #pragma unroll
    for (int p = 0; p < 4; p++)
        #pragma unroll
        for (int c = 0; c < 4; c++) acc2[p][c] = 0ull;

    const float* xp = Xs + rt * 8;
    const float* wp = Ws + ct * 4;

    #pragma unroll 4
    for (int k = 0; k < 128; k++) {
        const float* xr = xp + k * XST;
        u64 a0 = *(const u64*)(xr + 0);
        u64 a1 = *(const u64*)(xr + 2);
        u64 a2 = *(const u64*)(xr + 4);
        u64 a3 = *(const u64*)(xr + 6);
        float4 b = *(const float4*)(wp + k * N);
        u64 bx = pack2(b.x, b.x);
        u64 by = pack2(b.y, b.y);
        u64 bz = pack2(b.z, b.z);
        u64 bw = pack2(b.w, b.w);
        fma2(acc2[0][0], a0, bx); fma2(acc2[0][1], a0, by);
        fma2(acc2[0][2], a0, bz); fma2(acc2[0][3], a0, bw);
        fma2(acc2[1][0], a1, bx); fma2(acc2[1][1], a1, by);
        fma2(acc2[1][2], a1, bz); fma2(acc2[1][3], a1, bw);
        fma2(acc2[2][0], a2, bx); fma2(acc2[2][1], a2, by);
        fma2(acc2[2][2], a2, bz); fma2(acc2[2][3], a2, bw);
        fma2(acc2[3][0], a3, bx); fma2(acc2[3][1], a3, by);
        fma2(acc2[3][2], a3, bz); fma2(acc2[3][3], a3, bw);
    }

    #pragma unroll
    for (int p = 0; p < 4; p++) {
        float4 lo, hi;
        unpack2(acc2[p][0], lo.x, hi.x);
        unpack2(acc2[p][1], lo.y, hi.y);
        unpack2(acc2[p][2], lo.z, hi.z);
        unpack2(acc2[p][3], lo.w, hi.w);
        int gr = row0 + rt * 8 + 2 * p;
        if (gr < M) {
            uint2 o;
            o.x = h2_as_u32(__floats2half2_rn(lo.x, lo.y));
            o.y = h2_as_u32(__floats2half2_rn(lo.z, lo.w));
            ((uint2*)(Y + (size_t)gr * N))[ct] = o;
        }
        if (gr + 1 < M) {
            uint2 o;
            o.x = h2_as_u32(__floats2half2_rn(hi.x, hi.y));
            o.y = h2_as_u32(__floats2half2_rn(hi.z, hi.w));
            ((uint2*)(Y + (size_t)(gr + 1) * N))[ct] = o;
        }
    }
}

// ---------------- CSR gather over fp16 messages, fp32 accumulation ----------
__device__ __forceinline__ void acc8(float2 a[4], uint4 v) {
    float2 f0 = __half22float2(u32_as_h2(v.x));
    float2 f1 = __half22float2(u32_as_h2(v.y));
    float2 f2 = __half22float2(u32_as_h2(v.z));
    float2 f3 = __half22float2(u32_as_h2(v.w));
    a[0].x += f0.x; a[0].y += f0.y;
    a[1].x += f1.x; a[1].y += f1.y;
    a[2].x += f2.x; a[2].y += f2.y;
    a[3].x += f3.x; a[3].y += f3.y;
}

// D=128 fp16: row = 16 uint4. 16 lanes per node, 8 channels per lane.
__global__ __launch_bounds__(256)
void k_gather128(const __half* __restrict__ h, const float* __restrict__ b1,
                 float* __restrict__ out, int M)
{
    int gid  = blockIdx.x * blockDim.x + threadIdx.x;
    int node = gid >> 4;
    int lane = gid & 15;
    if (node >= M) return;

    const int beg = g_off[node];
    const int end = g_off[node + 1];
    const uint4* h4 = (const uint4*)h;

    float2 a[4] = {{0.f,0.f},{0.f,0.f},{0.f,0.f},{0.f,0.f}};

    int j = beg;
    for (; j + 4 <= end; j += 4) {
        int s0 = g_esrc[j + 0], s1 = g_esrc[j + 1];
        int s2 = g_esrc[j + 2], s3 = g_esrc[j + 3];
        uint4 v0 = h4[(size_t)s0 * 16 + lane];
        uint4 v1 = h4[(size_t)s1 * 16 + lane];
        uint4 v2 = h4[(size_t)s2 * 16 + lane];
        uint4 v3 = h4[(size_t)s3 * 16 + lane];
        acc8(a, v0); acc8(a, v1); acc8(a, v2); acc8(a, v3);
    }
    for (; j < end; j++) {
        int s = g_esrc[j];
        acc8(a, h4[(size_t)s * 16 + lane]);
    }

    float nn = g_inorm[node];
    const float4* b4 = (const float4*)b1;       // cols lane*8 .. lane*8+7
    float4 bb0 = b4[lane * 2 + 0];
    float4 bb1 = b4[lane * 2 + 1];
    float4 r0, r1;
    r0.x = fmaxf(fmaf(a[0].x, nn, bb0.x), 0.f);
    r0.y = fmaxf(fmaf(a[0].y, nn, bb0.y), 0.f);
    r0.z = fmaxf(fmaf(a[1].x, nn, bb0.z), 0.f);
    r0.w = fmaxf(fmaf(a[1].y, nn, bb0.w), 0.f);
    r1.x = fmaxf(fmaf(a[2].x, nn, bb1.x), 0.f);
    r1.y = fmaxf(fmaf(a[2].y, nn, bb1.y), 0.f);
    r1.z = fmaxf(fmaf(a[3].x, nn, bb1.z), 0.f);
    r1.w = fmaxf(fmaf(a[3].y, nn, bb1.w), 0.f);
    float4* o4 = (float4*)(out + (size_t)node * 128);
    o4[lane * 2 + 0] = r0;
    o4[lane * 2 + 1] = r1;
}

// D=64 fp16: row = 8 uint4. 8 lanes per node, 8 channels per lane.
__global__ __launch_bounds__(256)
void k_gather64(const __half* __restrict__ h, const float* __restrict__ b2,
                float* __restrict__ out, int M)
{
    int gid  = blockIdx.x * blockDim.x + threadIdx.x;
    int node = gid >> 3;
    int sub  = gid & 7;
    if (node >= M) return;

    const int beg = g_off[node];
    const int end = g_off[node + 1];
    const uint4* h4 = (const uint4*)h;

    float2 a[4] = {{0.f,0.f},{0.f,0.f},{0.f,0.f},{0.f,0.f}};

    int j = beg;
    for (; j + 4 <= end; j += 4) {
        int s0 = g_esrc[j + 0], s1 = g_esrc[j + 1];
        int s2 = g_esrc[j + 2], s3 = g_esrc[j + 3];
        uint4 v0 = h4[(size_t)s0 * 8 + sub];
        uint4 v1 = h4[(size_t)s1 * 8 + sub];
        uint4 v2 = h4[(size_t)s2 * 8 + sub];
        uint4 v3 = h4[(size_t)s3 * 8 + sub];
        acc8(a, v0); acc8(a, v1); acc8(a, v2); acc8(a, v3);
    }
    for (; j < end; j++) {
        int s = g_esrc[j];
        acc8(a, h4[(size_t)s * 8 + sub]);
    }

    float nn = g_inorm[node];
    const float4* b4 = (const float4*)b2;
    float4 bb0 = b4[sub * 2 + 0];
    float4 bb1 = b4[sub * 2 + 1];
    float4 r0, r1;
    r0.x = fmaf(a[0].x, nn, bb0.x);
    r0.y = fmaf(a[0].y, nn, bb0.y);
    r0.z = fmaf(a[1].x, nn, bb0.z);
    r0.w = fmaf(a[1].y, nn, bb0.w);
    r1.x = fmaf(a[2].x, nn, bb1.x);
    r1.y = fmaf(a[2].y, nn, bb1.y);
    r1.z = fmaf(a[3].x, nn, bb1.z);
    r1.w = fmaf(a[3].y, nn, bb1.w);
    float4* o4 = (float4*)(out + (size_t)node * 64);
    o4[sub * 2 + 0] = r0;
    o4[sub * 2 + 1] = r1;
}

// ---------------- launch ----------------------------------------------------
extern "C" void kernel_launch(void* const* d_in, const int* in_sizes, int n_in,
                              void* d_out, int out_size)
{
    const float* feat = (const float*)d_in[0];
    const int*   src  = (const int*)  d_in[1];
    const int*   dst  = (const int*)  d_in[2];
    const float* W1   = (const float*)d_in[3];
    const float* b1   = (const float*)d_in[4];
    const float* W2   = (const float*)d_in[5];
    const float* b2   = (const float*)d_in[6];
    float* out = (float*)d_out;

    const int M  = in_sizes[0] / IN_DIM;   // 100000
    const int nE = in_sizes[1];            // 1600000

    float *pA = nullptr, *pB = nullptr;
    cudaGetSymbolAddress((void**)&pA, g_bufA);
    cudaGetSymbolAddress((void**)&pB, g_bufB);
    __half* hA = (__half*)pA;              // fp16 message buffer

    constexpr int SMEM1 = (128 * 128 + 128 * (64 + 2)) * 4;
    constexpr int SMEM2 = (128 * 64 + 128 * (128 + 2)) * 4;
    cudaFuncSetAttribute(k_gemm<128, 64>,  cudaFuncAttributeMaxDynamicSharedMemorySize, SMEM1);
    cudaFuncSetAttribute(k_gemm<64, 128>,  cudaFuncAttributeMaxDynamicSharedMemorySize, SMEM2);

    static cudaStream_t s_side = nullptr;
    static cudaEvent_t  s_evFork = nullptr, s_evJoin = nullptr;
    if (!s_side) {
        cudaStreamCreateWithFlags(&s_side, cudaStreamNonBlocking);
        cudaEventCreateWithFlags(&s_evFork, cudaEventDisableTiming);
        cudaEventCreateWithFlags(&s_evJoin, cudaEventDisableTiming);
    }

    const int nb = (M + 1023) >> 10;

    // 1) degrees
    k_zero_counts<<<(M + 255) / 256, 256>>>(M);
    k_count<<<(nE + 255) / 256, 256>>>(src, dst, nE);
    cudaEventRecord(s_evFork, 0);

    // side stream: CSR build
    cudaStreamWaitEvent(s_side, s_evFork, 0);
    k_scan1<<<nb, 1024, 0, s_side>>>(M);
    k_scan2<<<1, 256, 0, s_side>>>(nb);
    k_scan3<<<(M + 255) / 256, 256, 0, s_side>>>(M, nE);
    k_fill<<<(nE + 255) / 256, 256, 0, s_side>>>(src, dst, nE);
    cudaEventRecord(s_evJoin, s_side);

    // main stream: norms + gemm1 (fp16 out)
    k_norm<<<(M + 255) / 256, 256>>>(M);
    k_gemm<128, 64><<<(M + 63) / 64, 256, SMEM1>>>(feat, W1, hA, M);

    cudaStreamWaitEvent(0, s_evJoin, 0);
    k_gather128<<<((size_t)M * 16 + 255) / 256, 256>>>(hA, b1, pB, M);

    // layer 2
    k_gemm<64, 128><<<(M + 127) / 128, 256, SMEM2>>>(pB, W2, hA, M);
    k_gather64<<<((size_t)M * 8 + 255) / 256, 256>>>(hA, b2, out, M);
}

// round 9
// speedup vs baseline: 2.1697x; 1.0461x over previous
#include <cuda_runtime.h>
#include <cuda_fp16.h>
#include <mma.h>
#include <cstdint>

using namespace nvcuda;

#define MAX_NODES 100000
#define MAX_EDGES 1700000
#define IN_DIM   128
#define HID_DIM  128
#define OUT_DIM  64

// ---------------- scratch (no allocs allowed -> device globals) -------------
__device__ float g_bufA[MAX_NODES * 128];   // h1 / h2 (as __half)
__device__ float g_bufB[MAX_NODES * 128];   // x1 (fp32)
__device__ float g_onorm[MAX_NODES];
__device__ float g_inorm[MAX_NODES];
__device__ int   g_indeg[MAX_NODES];
__device__ int   g_outdeg[MAX_NODES];
__device__ int   g_off[MAX_NODES + 1];
__device__ int   g_cur[MAX_NODES];
__device__ int   g_esrc[MAX_EDGES];
__device__ int   g_bsum[256];
__device__ int   g_bbase[256];
__device__ __align__(16) __half g_W1h[128 * 128];   // W1 fp16 [k][n]
__device__ __align__(16) __half g_W2h[128 * 64];    // W2 fp16 [k][n]

// ---------------- bit casts --------------------------------------------------
__device__ __forceinline__ unsigned h2_as_u32(__half2 h) {
    return *reinterpret_cast<unsigned*>(&h);
}
__device__ __forceinline__ __half2 u32_as_h2(unsigned u) {
    return *reinterpret_cast<__half2*>(&u);
}

// ---------------- degree / CSR build ---------------------------------------
__global__ void k_zero_counts(int n) {
    int i = blockIdx.x * blockDim.x + threadIdx.x;
    if (i < n) { g_indeg[i] = 0; g_outdeg[i] = 0; }
}

__global__ void k_count(const int* __restrict__ src, const int* __restrict__ dst, int nE) {
    int e = blockIdx.x * blockDim.x + threadIdx.x;
    if (e < nE) {
        atomicAdd(&g_indeg[dst[e]], 1);
        atomicAdd(&g_outdeg[src[e]], 1);
    }
}

__global__ void k_norm(int n) {
    int i = blockIdx.x * blockDim.x + threadIdx.x;
    if (i < n) {
        g_onorm[i] = rsqrtf(fmaxf((float)g_outdeg[i], 1.f));
        g_inorm[i] = rsqrtf(fmaxf((float)g_indeg[i],  1.f));
    }
}

__global__ void k_scan1(int n) {
    __shared__ int sm[1024];
    int t = threadIdx.x;
    int i = blockIdx.x * 1024 + t;
    int v = (i < n) ? g_indeg[i] : 0;
    sm[t] = v;
    __syncthreads();
    #pragma unroll
    for (int d = 1; d < 1024; d <<= 1) {
        int u = (t >= d) ? sm[t - d] : 0;
        __syncthreads();
        sm[t] += u;
        __syncthreads();
    }
    if (i < n) g_off[i] = sm[t] - v;
    if (t == 1023) g_bsum[blockIdx.x] = sm[1023];
}

__global__ void k_scan2(int nb) {
    __shared__ int sm[256];
    int t = threadIdx.x;
    int v = (t < nb) ? g_bsum[t] : 0;
    sm[t] = v;
    __syncthreads();
    #pragma unroll
    for (int d = 1; d < 256; d <<= 1) {
        int u = (t >= d) ? sm[t - d] : 0;
        __syncthreads();
        sm[t] += u;
        __syncthreads();
    }
    if (t < nb) g_bbase[t] = sm[t] - v;
}

__global__ void k_scan3(int n, int nE) {
    int i = blockIdx.x * blockDim.x + threadIdx.x;
    if (i < n) {
        int o = g_off[i] + g_bbase[i >> 10];
        g_off[i] = o;
        g_cur[i] = o;
    }
    if (i == 0) g_off[n] = nE;
}

__global__ void k_fill(const int* __restrict__ src, const int* __restrict__ dst, int nE) {
    int e = blockIdx.x * blockDim.x + threadIdx.x;
    if (e < nE) {
        int slot = atomicAdd(&g_cur[dst[e]], 1);
        g_esrc[slot] = src[e];
    }
}

// ---------------- weight fp16 convert (layout unchanged: [k][n]) ------------
__global__ void k_wh(const float* __restrict__ W, __half* __restrict__ Wh, int n) {
    int i = blockIdx.x * blockDim.x + threadIdx.x;
    if (i < n) Wh[i] = __float2half(W[i]);
}

// ---------------- wmma GEMM: Y[M,N] = (X[M,128]*onorm) @ W[128,N], fp16 out --
// 256 threads = 8 warps. CTA tile 128 x N, K=128. fp16 A/B, fp32 accum.
template<int N>
__global__ __launch_bounds__(256)
void k_tgemm(const float* __restrict__ X, const __half* __restrict__ Wh,
             __half* __restrict__ Y, int M)
{
    extern __shared__ char smem[];
    constexpr int LDA = 136;                     // halves (272B row, 16B-multiple)
    constexpr int LDB = N + 8;                   // halves
    __half* As = (__half*)smem;                  // [128][LDA]
    __half* Bs = As + 128 * LDA;                 // [128][LDB]
    float*  stg = (float*)(Bs + 128 * LDB);      // [8 warps][16*20]

    const int tid  = threadIdx.x;
    const int wid  = tid >> 5;
    const int lane = tid & 31;
    const int row0 = blockIdx.x * 128;

    // ---- B tile: W fp16, already [k][n] row-major ----
    constexpr int BC8 = N / 8;                   // uint4 chunks per row
    for (int i = tid; i < 128 * BC8; i += 256) {
        int r = i / BC8, c8 = i % BC8;
        uint4 v = ((const uint4*)(Wh + r * N))[c8];
        *(uint4*)(Bs + r * LDB + c8 * 8) = v;
    }

    // ---- A tile: X rows scaled by onorm, fp16 ----
    for (int i = tid; i < 128 * 16; i += 256) {
        int r = i >> 4, g = i & 15;              // g: 8-col group
        int gr = row0 + r;
        float4 v0 = make_float4(0.f, 0.f, 0.f, 0.f);
        float4 v1 = make_float4(0.f, 0.f, 0.f, 0.f);
        float sc = 0.f;
        if (gr < M) {
            const float4* xp = (const float4*)(X + (size_t)gr * 128 + g * 8);
            v0 = xp[0]; v1 = xp[1];
            sc = g_onorm[gr];
        }
        uint4 o;
        o.x = h2_as_u32(__floats2half2_rn(v0.x * sc, v0.y * sc));
        o.y = h2_as_u32(__floats2half2_rn(v0.z * sc, v0.w * sc));
        o.z = h2_as_u32(__floats2half2_rn(v1.x * sc, v1.y * sc));
        o.w = h2_as_u32(__floats2half2_rn(v1.z * sc, v1.w * sc));
        *(uint4*)(As + r * LDA + g * 8) = o;
    }
    __syncthreads();

    // ---- compute: each warp owns rows [wid*16, wid*16+16) x all N cols ----
    wmma::fragment<wmma::accumulator, 16, 16, 16, float> acc[N / 16];
    #pragma unroll
    for (int n = 0; n < N / 16; n++) wmma::fill_fragment(acc[n], 0.f);

    #pragma unroll
    for (int k = 0; k < 8; k++) {
        wmma::fragment<wmma::matrix_a, 16, 16, 16, __half, wmma::row_major> af;
        wmma::load_matrix_sync(af, As + (wid * 16) * LDA + k * 16, LDA);
        #pragma unroll
        for (int n = 0; n < N / 16; n++) {
            wmma::fragment<wmma::matrix_b, 16, 16, 16, __half, wmma::row_major> bf;
            wmma::load_matrix_sync(bf, Bs + (k * 16) * LDB + n * 16, LDB);
            wmma::mma_sync(acc[n], af, bf, acc[n]);
        }
    }

    // ---- epilogue: stage fp32 per 16x16 tile, pack fp16, coalesced store ----
    float* ws = stg + wid * (16 * 20);
    const int r  = lane >> 1;                    // 0..15
    const int c0 = (lane & 1) * 8;               // 0 or 8
    const int gr = row0 + wid * 16 + r;
    #pragma unroll
    for (int n = 0; n < N / 16; n++) {
        wmma::store_matrix_sync(ws, acc[n], 20, wmma::mem_row_major);
        __syncwarp();
        const float* p = ws + r * 20 + c0;
        uint4 o;
        o.x = h2_as_u32(__floats2half2_rn(p[0], p[1]));
        o.y = h2_as_u32(__floats2half2_rn(p[2], p[3]));
        o.z = h2_as_u32(__floats2half2_rn(p[4], p[5]));
        o.w = h2_as_u32(__floats2half2_rn(p[6], p[7]));
        if (gr < M)
            *(uint4*)(Y + (size_t)gr * N + n * 16 + c0) = o;
        __syncwarp();
    }
}

// ---------------- CSR gather over fp16 messages, fp32 accumulation ----------
__device__ __forceinline__ void acc8(float2 a[4], uint4 v) {
    float2 f0 = __half22float2(u32_as_h2(v.x));
    float2 f1 = __half22float2(u32_as_h2(v.y));
    float2 f2 = __half22float2(u32_as_h2(v.z));
    float2 f3 = __half22float2(u32_as_h2(v.w));
    a[0].x += f0.x; a[0].y += f0.y;
    a[1].x += f1.x; a[1].y += f1.y;
    a[2].x += f2.x; a[2].y += f2.y;
    a[3].x += f3.x; a[3].y += f3.y;
}

__global__ __launch_bounds__(256)
void k_gather128(const __half* __restrict__ h, const float* __restrict__ b1,
                 float* __restrict__ out, int M)
{
    int gid  = blockIdx.x * blockDim.x + threadIdx.x;
    int node = gid >> 4;
    int lane = gid & 15;
    if (node >= M) return;

    const int beg = g_off[node];
    const int end = g_off[node + 1];
    const uint4* h4 = (const uint4*)h;

    float2 a[4] = {{0.f,0.f},{0.f,0.f},{0.f,0.f},{0.f,0.f}};

    int j = beg;
    for (; j + 4 <= end; j += 4) {
        int s0 = g_esrc[j + 0], s1 = g_esrc[j + 1];
        int s2 = g_esrc[j + 2], s3 = g_esrc[j + 3];
        uint4 v0 = h4[(size_t)s0 * 16 + lane];
        uint4 v1 = h4[(size_t)s1 * 16 + lane];
        uint4 v2 = h4[(size_t)s2 * 16 + lane];
        uint4 v3 = h4[(size_t)s3 * 16 + lane];
        acc8(a, v0); acc8(a, v1); acc8(a, v2); acc8(a, v3);
    }
    for (; j < end; j++) {
        int s = g_esrc[j];
        acc8(a, h4[(size_t)s * 16 + lane]);
    }

    float nn = g_inorm[node];
    const float4* b4 = (const float4*)b1;
    float4 bb0 = b4[lane * 2 + 0];
    float4 bb1 = b4[lane * 2 + 1];
    float4 r0, r1;
    r0.x = fmaxf(fmaf(a[0].x, nn, bb0.x), 0.f);
    r0.y = fmaxf(fmaf(a[0].y, nn, bb0.y), 0.f);
    r0.z = fmaxf(fmaf(a[1].x, nn, bb0.z), 0.f);
    r0.w = fmaxf(fmaf(a[1].y, nn, bb0.w), 0.f);
    r1.x = fmaxf(fmaf(a[2].x, nn, bb1.x), 0.f);
    r1.y = fmaxf(fmaf(a[2].y, nn, bb1.y), 0.f);
    r1.z = fmaxf(fmaf(a[3].x, nn, bb1.z), 0.f);
    r1.w = fmaxf(fmaf(a[3].y, nn, bb1.w), 0.f);
    float4* o4 = (float4*)(out + (size_t)node * 128);
    o4[lane * 2 + 0] = r0;
    o4[lane * 2 + 1] = r1;
}

__global__ __launch_bounds__(256)
void k_gather64(const __half* __restrict__ h, const float* __restrict__ b2,
                float* __restrict__ out, int M)
{
    int gid  = blockIdx.x * blockDim.x + threadIdx.x;
    int node = gid >> 3;
    int sub  = gid & 7;
    if (node >= M) return;

    const int beg = g_off[node];
    const int end = g_off[node + 1];
    const uint4* h4 = (const uint4*)h;

    float2 a[4] = {{0.f,0.f},{0.f,0.f},{0.f,0.f},{0.f,0.f}};

    int j = beg;
    for (; j + 4 <= end; j += 4) {
        int s0 = g_esrc[j + 0], s1 = g_esrc[j + 1];
        int s2 = g_esrc[j + 2], s3 = g_esrc[j + 3];
        uint4 v0 = h4[(size_t)s0 * 8 + sub];
        uint4 v1 = h4[(size_t)s1 * 8 + sub];
        uint4 v2 = h4[(size_t)s2 * 8 + sub];
        uint4 v3 = h4[(size_t)s3 * 8 + sub];
        acc8(a, v0); acc8(a, v1); acc8(a, v2); acc8(a, v3);
    }
    for (; j < end; j++) {
        int s = g_esrc[j];
        acc8(a, h4[(size_t)s * 8 + sub]);
    }

    float nn = g_inorm[node];
    const float4* b4 = (const float4*)b2;
    float4 bb0 = b4[sub * 2 + 0];
    float4 bb1 = b4[sub * 2 + 1];
    float4 r0, r1;
    r0.x = fmaf(a[0].x, nn, bb0.x);
    r0.y = fmaf(a[0].y, nn, bb0.y);
    r0.z = fmaf(a[1].x, nn, bb0.z);
    r0.w = fmaf(a[1].y, nn, bb0.w);
    r1.x = fmaf(a[2].x, nn, bb1.x);
    r1.y = fmaf(a[2].y, nn, bb1.y);
    r1.z = fmaf(a[3].x, nn, bb1.z);
    r1.w = fmaf(a[3].y, nn, bb1.w);
    float4* o4 = (float4*)(out + (size_t)node * 64);
    o4[sub * 2 + 0] = r0;
    o4[sub * 2 + 1] = r1;
}

// ---------------- launch ----------------------------------------------------
extern "C" void kernel_launch(void* const* d_in, const int* in_sizes, int n_in,
                              void* d_out, int out_size)
{
    const float* feat = (const float*)d_in[0];
    const int*   src  = (const int*)  d_in[1];
    const int*   dst  = (const int*)  d_in[2];
    const float* W1   = (const float*)d_in[3];
    const float* b1   = (const float*)d_in[4];
    const float* W2   = (const float*)d_in[5];
    const float* b2   = (const float*)d_in[6];
    float* out = (float*)d_out;

    const int M  = in_sizes[0] / IN_DIM;   // 100000
    const int nE = in_sizes[1];            // 1600000

    float *pA = nullptr, *pB = nullptr;
    __half *w1h = nullptr, *w2h = nullptr;
    cudaGetSymbolAddress((void**)&pA, g_bufA);
    cudaGetSymbolAddress((void**)&pB, g_bufB);
    cudaGetSymbolAddress((void**)&w1h, g_W1h);
    cudaGetSymbolAddress((void**)&w2h, g_W2h);
    __half* hA = (__half*)pA;

    // smem: A + B + staging
    constexpr int TSM1 = (128 * 136 + 128 * (128 + 8)) * 2 + 8 * 16 * 20 * 4; // 79872
    constexpr int TSM2 = (128 * 136 + 128 * (64 + 8)) * 2 + 8 * 16 * 20 * 4;  // 63488
    cudaFuncSetAttribute(k_tgemm<128>, cudaFuncAttributeMaxDynamicSharedMemorySize, TSM1);
    cudaFuncSetAttribute(k_tgemm<64>,  cudaFuncAttributeMaxDynamicSharedMemorySize, TSM2);

    static cudaStream_t s_side = nullptr;
    static cudaEvent_t  s_evFork = nullptr, s_evJoin = nullptr;
    if (!s_side) {
        cudaStreamCreateWithFlags(&s_side, cudaStreamNonBlocking);
        cudaEventCreateWithFlags(&s_evFork, cudaEventDisableTiming);
        cudaEventCreateWithFlags(&s_evJoin, cudaEventDisableTiming);
    }

    const int nb = (M + 1023) >> 10;
    const int ng = (M + 127) / 128;        // 782 tiles

    // 0) fp16 weight convert (tiny)
    k_wh<<<(128 * 128 + 255) / 256, 256>>>(W1, w1h, 128 * 128);
    k_wh<<<(128 * 64 + 255) / 256, 256>>>(W2, w2h, 128 * 64);

    // 1) degrees
    k_zero_counts<<<(M + 255) / 256, 256>>>(M);
    k_count<<<(nE + 255) / 256, 256>>>(src, dst, nE);
    cudaEventRecord(s_evFork, 0);

    // side stream: CSR build
    cudaStreamWaitEvent(s_side, s_evFork, 0);
    k_scan1<<<nb, 1024, 0, s_side>>>(M);
    k_scan2<<<1, 256, 0, s_side>>>(nb);
    k_scan3<<<(M + 255) / 256, 256, 0, s_side>>>(M, nE);
    k_fill<<<(nE + 255) / 256, 256, 0, s_side>>>(src, dst, nE);
    cudaEventRecord(s_evJoin, s_side);

    // main stream: norms + wmma gemm1 (fp16 out)
    k_norm<<<(M + 255) / 256, 256>>>(M);
    k_tgemm<128><<<ng, 256, TSM1>>>(feat, w1h, hA, M);

    cudaStreamWaitEvent(0, s_evJoin, 0);
    k_gather128<<<((size_t)M * 16 + 255) / 256, 256>>>(hA, b1, pB, M);

    // layer 2
    k_tgemm<64><<<ng, 256, TSM2>>>(pB, w2h, hA, M);
    k_gather64<<<((size_t)M * 8 + 255) / 256, 256>>>(hA, b2, out, M);
}

// round 11
// speedup vs baseline: 3.2740x; 1.5090x over previous
#include <cuda_runtime.h>
#include <cuda_fp16.h>
#include <mma.h>
#include <cstdint>

using namespace nvcuda;

#define MAX_NODES 100000
#define MAX_EDGES 1700000
#define IN_DIM   128

// ---------------- scratch (no allocs allowed -> device globals) -------------
__device__ float g_bufA[MAX_NODES * 128];   // h1 / h2 (as __half)
__device__ float g_bufB[MAX_NODES * 128];   // x1 (as __half)
__device__ int   g_indeg[MAX_NODES];
__device__ int   g_outdeg[MAX_NODES];
__device__ int   g_off[MAX_NODES + 1];
__device__ int   g_cur[MAX_NODES];
__device__ int   g_esrc[MAX_EDGES];
__device__ int   g_bsum[256];
__device__ int   g_bbase[256];
__device__ __align__(16) __half g_W1h[128 * 128];   // W1 fp16 [k][n]
__device__ __align__(16) __half g_W2h[128 * 64];    // W2 fp16 [k][n]

// ---------------- bit casts --------------------------------------------------
__device__ __forceinline__ unsigned h2_as_u32(__half2 h) {
    return *reinterpret_cast<unsigned*>(&h);
}
__device__ __forceinline__ __half2 u32_as_h2(unsigned u) {
    return *reinterpret_cast<__half2*>(&u);
}

// ---------------- prep: zero counts + fp16 weight converts (one kernel) -----
__global__ void k_prep(const float* __restrict__ W1, const float* __restrict__ W2, int n) {
    int i = blockIdx.x * blockDim.x + threadIdx.x;
    if (i < n) { g_indeg[i] = 0; g_outdeg[i] = 0; }
    if (i < 128 * 128) g_W1h[i] = __float2half(W1[i]);
    if (i < 128 * 64)  g_W2h[i] = __float2half(W2[i]);
}

// ---------------- degree count: 4 edges / thread -----------------------------
__global__ void k_count(const int* __restrict__ src, const int* __restrict__ dst, int nE) {
    int i = blockIdx.x * blockDim.x + threadIdx.x;
    int base = i * 4;
    if (base + 3 < nE) {
        int4 s = ((const int4*)src)[i];
        int4 d = ((const int4*)dst)[i];
        atomicAdd(&g_outdeg[s.x], 1); atomicAdd(&g_indeg[d.x], 1);
        atomicAdd(&g_outdeg[s.y], 1); atomicAdd(&g_indeg[d.y], 1);
        atomicAdd(&g_outdeg[s.z], 1); atomicAdd(&g_indeg[d.z], 1);
        atomicAdd(&g_outdeg[s.w], 1); atomicAdd(&g_indeg[d.w], 1);
    } else {
        for (int e = base; e < nE; e++) {
            atomicAdd(&g_outdeg[src[e]], 1);
            atomicAdd(&g_indeg[dst[e]], 1);
        }
    }
}

// ---------------- hierarchical exclusive scan of indeg -----------------------
__global__ void k_scan1(int n) {
    __shared__ int sm[1024];
    int t = threadIdx.x;
    int i = blockIdx.x * 1024 + t;
    int v = (i < n) ? g_indeg[i] : 0;
    sm[t] = v;
    __syncthreads();
    #pragma unroll
    for (int d = 1; d < 1024; d <<= 1) {
        int u = (t >= d) ? sm[t - d] : 0;
        __syncthreads();
        sm[t] += u;
        __syncthreads();
    }
    if (i < n) g_off[i] = sm[t] - v;
    if (t == 1023) g_bsum[blockIdx.x] = sm[1023];
}

__global__ void k_scan2(int nb) {
    __shared__ int sm[256];
    int t = threadIdx.x;
    int v = (t < nb) ? g_bsum[t] : 0;
    sm[t] = v;
    __syncthreads();
    #pragma unroll
    for (int d = 1; d < 256; d <<= 1) {
        int u = (t >= d) ? sm[t - d] : 0;
        __syncthreads();
        sm[t] += u;
        __syncthreads();
    }
    if (t < nb) g_bbase[t] = sm[t] - v;
}

__global__ void k_scan3(int n, int nE) {
    int i = blockIdx.x * blockDim.x + threadIdx.x;
    if (i < n) {
        int o = g_off[i] + g_bbase[i >> 10];
        g_off[i] = o;
        g_cur[i] = o;
    }
    if (i == 0) g_off[n] = nE;
}

// ---------------- CSR fill: 2 edges / thread ---------------------------------
__global__ void k_fill(const int* __restrict__ src, const int* __restrict__ dst, int nE) {
    int i = blockIdx.x * blockDim.x + threadIdx.x;
    int base = i * 2;
    if (base + 1 < nE) {
        int2 s = ((const int2*)src)[i];
        int2 d = ((const int2*)dst)[i];
        int p0 = atomicAdd(&g_cur[d.x], 1);
        int p1 = atomicAdd(&g_cur[d.y], 1);
        g_esrc[p0] = s.x;
        g_esrc[p1] = s.y;
    } else if (base < nE) {
        int slot = atomicAdd(&g_cur[dst[base]], 1);
        g_esrc[slot] = src[base];
    }
}

// ---------------- wmma GEMM: Y[M,N] = (X[M,128]*rsqrt(outdeg)) @ W ----------
// 256 threads = 8 warps. CTA tile 128 x N, K=128. fp16 A/B, fp32 accum,
// fp16 output. XH: X is fp16 (x1) vs fp32 (features).
template<int N, bool XH>
__global__ __launch_bounds__(256)
void k_tgemm(const void* __restrict__ Xv, const __half* __restrict__ Wh,
             __half* __restrict__ Y, int M)
{
    extern __shared__ char smem[];
    constexpr int LDA = 136;
    constexpr int LDB = N + 8;
    __half* As = (__half*)smem;                  // [128][LDA]
    __half* Bs = As + 128 * LDA;                 // [128][LDB]
    float*  stg = (float*)(Bs + 128 * LDB);      // [8 warps][16*20]

    const int tid  = threadIdx.x;
    const int wid  = tid >> 5;
    const int lane = tid & 31;
    const int row0 = blockIdx.x * 128;

    // ---- B tile ----
    constexpr int BC8 = N / 8;
    for (int i = tid; i < 128 * BC8; i += 256) {
        int r = i / BC8, c8 = i % BC8;
        uint4 v = ((const uint4*)(Wh + r * N))[c8];
        *(uint4*)(Bs + r * LDB + c8 * 8) = v;
    }

    // ---- A tile: X rows scaled by rsqrt(outdeg), fp16 ----
    for (int i = tid; i < 128 * 16; i += 256) {
        int r = i >> 4, g = i & 15;              // g: 8-col group
        int gr = row0 + r;
        uint4 o = make_uint4(0u, 0u, 0u, 0u);
        if (gr < M) {
            float sc = rsqrtf(fmaxf((float)g_outdeg[gr], 1.f));
            if (XH) {
                uint4 v = ((const uint4*)((const __half*)Xv + (size_t)gr * 128))[g];
                float2 f0 = __half22float2(u32_as_h2(v.x));
                float2 f1 = __half22float2(u32_as_h2(v.y));
                float2 f2 = __half22float2(u32_as_h2(v.z));
                float2 f3 = __half22float2(u32_as_h2(v.w));
                o.x = h2_as_u32(__floats2half2_rn(f0.x * sc, f0.y * sc));
                o.y = h2_as_u32(__floats2half2_rn(f1.x * sc, f1.y * sc));
                o.z = h2_as_u32(__floats2half2_rn(f2.x * sc, f2.y * sc));
                o.w = h2_as_u32(__floats2half2_rn(f3.x * sc, f3.y * sc));
            } else {
                const float4* xp = (const float4*)((const float*)Xv + (size_t)gr * 128 + g * 8);
                float4 v0 = xp[0], v1 = xp[1];
                o.x = h2_as_u32(__floats2half2_rn(v0.x * sc, v0.y * sc));
                o.y = h2_as_u32(__floats2half2_rn(v0.z * sc, v0.w * sc));
                o.z = h2_as_u32(__floats2half2_rn(v1.x * sc, v1.y * sc));
                o.w = h2_as_u32(__floats2half2_rn(v1.z * sc, v1.w * sc));
            }
        }
        *(uint4*)(As + r * LDA + g * 8) = o;
    }
    __syncthreads();

    // ---- compute ----
    wmma::fragment<wmma::accumulator, 16, 16, 16, float> acc[N / 16];
    #pragma unroll
    for (int n = 0; n < N / 16; n++) wmma::fill_fragment(acc[n], 0.f);

    #pragma unroll
    for (int k = 0; k < 8; k++) {
        wmma::fragment<wmma::matrix_a, 16, 16, 16, __half, wmma::row_major> af;
        wmma::load_matrix_sync(af, As + (wid * 16) * LDA + k * 16, LDA);
        #pragma unroll
        for (int n = 0; n < N / 16; n++) {
            wmma::fragment<wmma::matrix_b, 16, 16, 16, __half, wmma::row_major> bf;
            wmma::load_matrix_sync(bf, Bs + (k * 16) * LDB + n * 16, LDB);
            wmma::mma_sync(acc[n], af, bf, acc[n]);
        }
    }

    // ---- epilogue ----
    float* ws = stg + wid * (16 * 20);
    const int r  = lane >> 1;
    const int c0 = (lane & 1) * 8;
    const int gr = row0 + wid * 16 + r;
    #pragma unroll
    for (int n = 0; n < N / 16; n++) {
        wmma::store_matrix_sync(ws, acc[n], 20, wmma::mem_row_major);
        __syncwarp();
        const float* p = ws + r * 20 + c0;
        uint4 o;
        o.x = h2_as_u32(__floats2half2_rn(p[0], p[1]));
        o.y = h2_as_u32(__floats2half2_rn(p[2], p[3]));
        o.z = h2_as_u32(__floats2half2_rn(p[4], p[5]));
        o.w = h2_as_u32(__floats2half2_rn(p[6], p[7]));
        if (gr < M)
            *(uint4*)(Y + (size_t)gr * N + n * 16 + c0) = o;
        __syncwarp();
    }
}

// ---------------- CSR gather over fp16 messages, fp32 accumulation ----------
__device__ __forceinline__ void acc8(float2 a[4], uint4 v) {
    float2 f0 = __half22float2(u32_as_h2(v.x));
    float2 f1 = __half22float2(u32_as_h2(v.y));
    float2 f2 = __half22float2(u32_as_h2(v.z));
    float2 f3 = __half22float2(u32_as_h2(v.w));
    a[0].x += f0.x; a[0].y += f0.y;
    a[1].x += f1.x; a[1].y += f1.y;
    a[2].x += f2.x; a[2].y += f2.y;
    a[3].x += f3.x; a[3].y += f3.y;
}

// D=128: 16 lanes/node, 8 channels/lane. relu(agg*inorm + b1) -> fp16 x1
__global__ __launch_bounds__(256)
void k_gather128(const __half* __restrict__ h, const float* __restrict__ b1,
                 __half* __restrict__ out, int M)
{
    int gid  = blockIdx.x * blockDim.x + threadIdx.x;
    int node = gid >> 4;
    int lane = gid & 15;
    if (node >= M) return;

    const int beg = g_off[node];
    const int end = g_off[node + 1];
    const uint4* h4 = (const uint4*)h;

    float2 a[4] = {{0.f,0.f},{0.f,0.f},{0.f,0.f},{0.f,0.f}};

    int j = beg;
    for (; j + 4 <= end; j += 4) {
        int s0 = g_esrc[j + 0], s1 = g_esrc[j + 1];
        int s2 = g_esrc[j + 2], s3 = g_esrc[j + 3];
        uint4 v0 = h4[(size_t)s0 * 16 + lane];
        uint4 v1 = h4[(size_t)s1 * 16 + lane];
        uint4 v2 = h4[(size_t)s2 * 16 + lane];
        uint4 v3 = h4[(size_t)s3 * 16 + lane];
        acc8(a, v0); acc8(a, v1); acc8(a, v2); acc8(a, v3);
    }
    for (; j < end; j++) {
        int s = g_esrc[j];
        acc8(a, h4[(size_t)s * 16 + lane]);
    }

    float nn = rsqrtf(fmaxf((float)(end - beg), 1.f));
    const float4* b4 = (const float4*)b1;
    float4 bb0 = b4[lane * 2 + 0];
    float4 bb1 = b4[lane * 2 + 1];
    float r0x = fmaxf(fmaf(a[0].x, nn, bb0.x), 0.f);
    float r0y = fmaxf(fmaf(a[0].y, nn, bb0.y), 0.f);
    float r0z = fmaxf(fmaf(a[1].x, nn, bb0.z), 0.f);
    float r0w = fmaxf(fmaf(a[1].y, nn, bb0.w), 0.f);
    float r1x = fmaxf(fmaf(a[2].x, nn, bb1.x), 0.f);
    float r1y = fmaxf(fmaf(a[2].y, nn, bb1.y), 0.f);
    float r1z = fmaxf(fmaf(a[3].x, nn, bb1.z), 0.f);
    float r1w = fmaxf(fmaf(a[3].y, nn, bb1.w), 0.f);
    uint4 o;
    o.x = h2_as_u32(__floats2half2_rn(r0x, r0y));
    o.y = h2_as_u32(__floats2half2_rn(r0z, r0w));
    o.z = h2_as_u32(__floats2half2_rn(r1x, r1y));
    o.w = h2_as_u32(__floats2half2_rn(r1z, r1w));
    ((uint4*)out)[(size_t)node * 16 + lane] = o;
}

// D=64: 8 lanes/node, 8 channels/lane. agg*inorm + b2 -> fp32 out
__global__ __launch_bounds__(256)
void k_gather64(const __half* __restrict__ h, const float* __restrict__ b2,
                float* __restrict__ out, int M)
{
    int gid  = blockIdx.x * blockDim.x + threadIdx.x;
    int node = gid >> 3;
    int sub  = gid & 7;
    if (node >= M) return;

    const int beg = g_off[node];
    const int end = g_off[node + 1];
    const uint4* h4 = (const uint4*)h;

    float2 a[4] = {{0.f,0.f},{0.f,0.f},{0.f,0.f},{0.f,0.f}};

    int j = beg;
    for (; j + 4 <= end; j += 4) {
        int s0 = g_esrc[j + 0], s1 = g_esrc[j + 1];
        int s2 = g_esrc[j + 2], s3 = g_esrc[j + 3];
        uint4 v0 = h4[(size_t)s0 * 8 + sub];
        uint4 v1 = h4[(size_t)s1 * 8 + sub];
        uint4 v2 = h4[(size_t)s2 * 8 + sub];
        uint4 v3 = h4[(size_t)s3 * 8 + sub];
        acc8(a, v0); acc8(a, v1); acc8(a, v2); acc8(a, v3);
    }
    for (; j < end; j++) {
        int s = g_esrc[j];
        acc8(a, h4[(size_t)s * 8 + sub]);
    }

    float nn = rsqrtf(fmaxf((float)(end - beg), 1.f));
    const float4* b4 = (const float4*)b2;
    float4 bb0 = b4[sub * 2 + 0];
    float4 bb1 = b4[sub * 2 + 1];
    float4 r0, r1;
    r0.x = fmaf(a[0].x, nn, bb0.x);
    r0.y = fmaf(a[0].y, nn, bb0.y);
    r0.z = fmaf(a[1].x, nn, bb0.z);
    r0.w = fmaf(a[1].y, nn, bb0.w);
    r1.x = fmaf(a[2].x, nn, bb1.x);
    r1.y = fmaf(a[2].y, nn, bb1.y);
    r1.z = fmaf(a[3].x, nn, bb1.z);
    r1.w = fmaf(a[3].y, nn, bb1.w);
    float4* o4 = (float4*)(out + (size_t)node * 64);
    o4[sub * 2 + 0] = r0;
    o4[sub * 2 + 1] = r1;
}

// ---------------- launch ----------------------------------------------------
extern "C" void kernel_launch(void* const* d_in, const int* in_sizes, int n_in,
                              void* d_out, int out_size)
{
    const float* feat = (const float*)d_in[0];
    const int*   src  = (const int*)  d_in[1];
    const int*   dst  = (const int*)  d_in[2];
    const float* W1   = (const float*)d_in[3];
    const float* b1   = (const float*)d_in[4];
    const float* W2   = (const float*)d_in[5];
    const float* b2   = (const float*)d_in[6];
    float* out = (float*)d_out;

    const int M  = in_sizes[0] / IN_DIM;   // 100000
    const int nE = in_sizes[1];            // 1600000

    float *pA = nullptr, *pB = nullptr;
    __half *w1h = nullptr, *w2h = nullptr;
    cudaGetSymbolAddress((void**)&pA, g_bufA);
    cudaGetSymbolAddress((void**)&pB, g_bufB);
    cudaGetSymbolAddress((void**)&w1h, g_W1h);   // device address (NOT host shadow)
    cudaGetSymbolAddress((void**)&w2h, g_W2h);
    __half* hA  = (__half*)pA;             // fp16 message buffer (h1/h2)
    __half* x1h = (__half*)pB;             // fp16 x1

    constexpr int TSM1 = (128 * 136 + 128 * (128 + 8)) * 2 + 8 * 16 * 20 * 4; // 79872
    constexpr int TSM2 = (128 * 136 + 128 * (64 + 8)) * 2 + 8 * 16 * 20 * 4;  // 63488
    cudaFuncSetAttribute((const void*)k_tgemm<128, false>,
                         cudaFuncAttributeMaxDynamicSharedMemorySize, TSM1);
    cudaFuncSetAttribute((const void*)k_tgemm<64, true>,
                         cudaFuncAttributeMaxDynamicSharedMemorySize, TSM2);

    static cudaStream_t s_side = nullptr;
    static cudaEvent_t  s_evFork = nullptr, s_evJoin = nullptr;
    if (!s_side) {
        cudaStreamCreateWithFlags(&s_side, cudaStreamNonBlocking);
        cudaEventCreateWithFlags(&s_evFork, cudaEventDisableTiming);
        cudaEventCreateWithFlags(&s_evJoin, cudaEventDisableTiming);
    }

    const int nb = (M + 1023) >> 10;
    const int ng = (M + 127) / 128;

    // 0) prep: zero counts + weight fp16 converts
    k_prep<<<(M + 255) / 256, 256>>>(W1, W2, M);

    // 1) degrees (4 edges/thread)
    k_count<<<(nE / 4 + 255) / 256, 256>>>(src, dst, nE);
    cudaEventRecord(s_evFork, 0);

    // side stream: CSR build
    cudaStreamWaitEvent(s_side, s_evFork, 0);
    k_scan1<<<nb, 1024, 0, s_side>>>(M);
    k_scan2<<<1, 256, 0, s_side>>>(nb);
    k_scan3<<<(M + 255) / 256, 256, 0, s_side>>>(M, nE);
    k_fill<<<(nE / 2 + 255) / 256, 256, 0, s_side>>>(src, dst, nE);
    cudaEventRecord(s_evJoin, s_side);

    // main stream: gemm1 (fp32 in, fp16 out)
    k_tgemm<128, false><<<ng, 256, TSM1>>>(feat, w1h, hA, M);

    cudaStreamWaitEvent(0, s_evJoin, 0);
    k_gather128<<<((size_t)M * 16 + 255) / 256, 256>>>(hA, b1, x1h, M);

    // layer 2: gemm2 (fp16 in, fp16 out)
    k_tgemm<64, true><<<ng, 256, TSM2>>>(x1h, w2h, hA, M);
    k_gather64<<<((size_t)M * 8 + 255) / 256, 256>>>(hA, b2, out, M);
}

// round 12
// speedup vs baseline: 3.3312x; 1.0175x over previous
#include <cuda_runtime.h>
#include <cuda_fp16.h>
#include <mma.h>
#include <cstdint>

using namespace nvcuda;

#define MAX_NODES 100000
#define MAX_EDGES 1700000
#define IN_DIM   128

// ---------------- scratch (no allocs allowed -> device globals) -------------
__device__ float g_bufA[MAX_NODES * 128];   // h1 / h2 (as __half)
__device__ float g_bufB[MAX_NODES * 128];   // x1 (as __half)
__device__ int   g_indeg[MAX_NODES];
__device__ int   g_outdeg[MAX_NODES];
__device__ int   g_off[MAX_NODES + 1];
__device__ int   g_cur[MAX_NODES];
__device__ int   g_esrc[MAX_EDGES];
__device__ int   g_bsum[256];
__device__ int   g_bbase[256];
__device__ __align__(16) __half g_W1h[128 * 128];   // W1 fp16 [k][n]
__device__ __align__(16) __half g_W2h[128 * 64];    // W2 fp16 [k][n]

// ---------------- bit casts --------------------------------------------------
__device__ __forceinline__ unsigned h2_as_u32(__half2 h) {
    return *reinterpret_cast<unsigned*>(&h);
}
__device__ __forceinline__ __half2 u32_as_h2(unsigned u) {
    return *reinterpret_cast<__half2*>(&u);
}

// ---------------- prep: zero counts (int4) + fp16 weight converts -----------
__global__ void k_prep(const float* __restrict__ W1, const float* __restrict__ W2, int n4) {
    int i = blockIdx.x * blockDim.x + threadIdx.x;
    if (i < n4) {
        ((int4*)g_indeg)[i]  = make_int4(0, 0, 0, 0);
        ((int4*)g_outdeg)[i] = make_int4(0, 0, 0, 0);
    }
    if (i < 128 * 128) g_W1h[i] = __float2half(W1[i]);
    if (i < 128 * 64)  g_W2h[i] = __float2half(W2[i]);
}

// ---------------- degree counts: 4 edges / thread, split by endpoint ---------
__global__ void k_count_src(const int* __restrict__ src, int nE) {
    int i = blockIdx.x * blockDim.x + threadIdx.x;
    int base = i * 4;
    if (base + 3 < nE) {
        int4 s = ((const int4*)src)[i];
        atomicAdd(&g_outdeg[s.x], 1);
        atomicAdd(&g_outdeg[s.y], 1);
        atomicAdd(&g_outdeg[s.z], 1);
        atomicAdd(&g_outdeg[s.w], 1);
    } else {
        for (int e = base; e < nE; e++) atomicAdd(&g_outdeg[src[e]], 1);
    }
}

__global__ void k_count_dst(const int* __restrict__ dst, int nE) {
    int i = blockIdx.x * blockDim.x + threadIdx.x;
    int base = i * 4;
    if (base + 3 < nE) {
        int4 d = ((const int4*)dst)[i];
        atomicAdd(&g_indeg[d.x], 1);
        atomicAdd(&g_indeg[d.y], 1);
        atomicAdd(&g_indeg[d.z], 1);
        atomicAdd(&g_indeg[d.w], 1);
    } else {
        for (int e = base; e < nE; e++) atomicAdd(&g_indeg[dst[e]], 1);
    }
}

// ---------------- hierarchical exclusive scan of indeg -----------------------
__global__ void k_scan1(int n) {
    __shared__ int sm[1024];
    int t = threadIdx.x;
    int i = blockIdx.x * 1024 + t;
    int v = (i < n) ? g_indeg[i] : 0;
    sm[t] = v;
    __syncthreads();
    #pragma unroll
    for (int d = 1; d < 1024; d <<= 1) {
        int u = (t >= d) ? sm[t - d] : 0;
        __syncthreads();
        sm[t] += u;
        __syncthreads();
    }
    if (i < n) g_off[i] = sm[t] - v;
    if (t == 1023) g_bsum[blockIdx.x] = sm[1023];
}

__global__ void k_scan2(int nb) {
    __shared__ int sm[256];
    int t = threadIdx.x;
    int v = (t < nb) ? g_bsum[t] : 0;
    sm[t] = v;
    __syncthreads();
    #pragma unroll
    for (int d = 1; d < 256; d <<= 1) {
        int u = (t >= d) ? sm[t - d] : 0;
        __syncthreads();
        sm[t] += u;
        __syncthreads();
    }
    if (t < nb) g_bbase[t] = sm[t] - v;
}

__global__ void k_scan3(int n, int nE) {
    int i = blockIdx.x * blockDim.x + threadIdx.x;
    if (i < n) {
        int o = g_off[i] + g_bbase[i >> 10];
        g_off[i] = o;
        g_cur[i] = o;
    }
    if (i == 0) g_off[n] = nE;
}

// ---------------- CSR fill: 2 edges / thread ---------------------------------
__global__ void k_fill(const int* __restrict__ src, const int* __restrict__ dst, int nE) {
    int i = blockIdx.x * blockDim.x + threadIdx.x;
    int base = i * 2;
    if (base + 1 < nE) {
        int2 s = ((const int2*)src)[i];
        int2 d = ((const int2*)dst)[i];
        int p0 = atomicAdd(&g_cur[d.x], 1);
        int p1 = atomicAdd(&g_cur[d.y], 1);
        g_esrc[p0] = s.x;
        g_esrc[p1] = s.y;
    } else if (base < nE) {
        int slot = atomicAdd(&g_cur[dst[base]], 1);
        g_esrc[slot] = src[base];
    }
}

// ---------------- wmma GEMM: Y[M,N] = (X[M,128]*rsqrt(outdeg)) @ W ----------
// 256 threads = 8 warps. CTA tile 128 x N, K=128. fp16 A/B, fp32 accum,
// fp16 output. XH: X is fp16 (x1) vs fp32 (features).
template<int N, bool XH>
__global__ __launch_bounds__(256)
void k_tgemm(const void* __restrict__ Xv, const __half* __restrict__ Wh,
             __half* __restrict__ Y, int M)
{
    extern __shared__ char smem[];
    constexpr int LDA = 136;
    constexpr int LDB = N + 8;
    __half* As = (__half*)smem;                  // [128][LDA]
    __half* Bs = As + 128 * LDA;                 // [128][LDB]
    float*  stg = (float*)(Bs + 128 * LDB);      // [8 warps][16*20]

    const int tid  = threadIdx.x;
    const int wid  = tid >> 5;
    const int lane = tid & 31;
    const int row0 = blockIdx.x * 128;

    // ---- B tile ----
    constexpr int BC8 = N / 8;
    for (int i = tid; i < 128 * BC8; i += 256) {
        int r = i / BC8, c8 = i % BC8;
        uint4 v = ((const uint4*)(Wh + r * N))[c8];
        *(uint4*)(Bs + r * LDB + c8 * 8) = v;
    }

    // ---- A tile: X rows scaled by rsqrt(outdeg), fp16 ----
    for (int i = tid; i < 128 * 16; i += 256) {
        int r = i >> 4, g = i & 15;              // g: 8-col group
        int gr = row0 + r;
        uint4 o = make_uint4(0u, 0u, 0u, 0u);
        if (gr < M) {
            float sc = rsqrtf(fmaxf((float)g_outdeg[gr], 1.f));
            if (XH) {
                uint4 v = ((const uint4*)((const __half*)Xv + (size_t)gr * 128))[g];
                float2 f0 = __half22float2(u32_as_h2(v.x));
                float2 f1 = __half22float2(u32_as_h2(v.y));
                float2 f2 = __half22float2(u32_as_h2(v.z));
                float2 f3 = __half22float2(u32_as_h2(v.w));
                o.x = h2_as_u32(__floats2half2_rn(f0.x * sc, f0.y * sc));
                o.y = h2_as_u32(__floats2half2_rn(f1.x * sc, f1.y * sc));
                o.z = h2_as_u32(__floats2half2_rn(f2.x * sc, f2.y * sc));
                o.w = h2_as_u32(__floats2half2_rn(f3.x * sc, f3.y * sc));
            } else {
                const float4* xp = (const float4*)((const float*)Xv + (size_t)gr * 128 + g * 8);
                float4 v0 = xp[0], v1 = xp[1];
                o.x = h2_as_u32(__floats2half2_rn(v0.x * sc, v0.y * sc));
                o.y = h2_as_u32(__floats2half2_rn(v0.z * sc, v0.w * sc));
                o.z = h2_as_u32(__floats2half2_rn(v1.x * sc, v1.y * sc));
                o.w = h2_as_u32(__floats2half2_rn(v1.z * sc, v1.w * sc));
            }
        }
        *(uint4*)(As + r * LDA + g * 8) = o;
    }
    __syncthreads();

    // ---- compute ----
    wmma::fragment<wmma::accumulator, 16, 16, 16, float> acc[N / 16];
    #pragma unroll
    for (int n = 0; n < N / 16; n++) wmma::fill_fragment(acc[n], 0.f);

    #pragma unroll
    for (int k = 0; k < 8; k++) {
        wmma::fragment<wmma::matrix_a, 16, 16, 16, __half, wmma::row_major> af;
        wmma::load_matrix_sync(af, As + (wid * 16) * LDA + k * 16, LDA);
        #pragma unroll
        for (int n = 0; n < N / 16; n++) {
            wmma::fragment<wmma::matrix_b, 16, 16, 16, __half, wmma::row_major> bf;
            wmma::load_matrix_sync(bf, Bs + (k * 16) * LDB + n * 16, LDB);
            wmma::mma_sync(acc[n], af, bf, acc[n]);
        }
    }

    // ---- epilogue ----
    float* ws = stg + wid * (16 * 20);
    const int r  = lane >> 1;
    const int c0 = (lane & 1) * 8;
    const int gr = row0 + wid * 16 + r;
    #pragma unroll
    for (int n = 0; n < N / 16; n++) {
        wmma::store_matrix_sync(ws, acc[n], 20, wmma::mem_row_major);
        __syncwarp();
        const float* p = ws + r * 20 + c0;
        uint4 o;
        o.x = h2_as_u32(__floats2half2_rn(p[0], p[1]));
        o.y = h2_as_u32(__floats2half2_rn(p[2], p[3]));
        o.z = h2_as_u32(__floats2half2_rn(p[4], p[5]));
        o.w = h2_as_u32(__floats2half2_rn(p[6], p[7]));
        if (gr < M)
            *(uint4*)(Y + (size_t)gr * N + n * 16 + c0) = o;
        __syncwarp();
    }
}

// ---------------- CSR gather over fp16 messages, fp32 accumulation ----------
__device__ __forceinline__ void acc8(float2 a[4], uint4 v) {
    float2 f0 = __half22float2(u32_as_h2(v.x));
    float2 f1 = __half22float2(u32_as_h2(v.y));
    float2 f2 = __half22float2(u32_as_h2(v.z));
    float2 f3 = __half22float2(u32_as_h2(v.w));
    a[0].x += f0.x; a[0].y += f0.y;
    a[1].x += f1.x; a[1].y += f1.y;
    a[2].x += f2.x; a[2].y += f2.y;
    a[3].x += f3.x; a[3].y += f3.y;
}

// D=128: 16 lanes/node, 8 channels/lane. relu(agg*inorm + b1) -> fp16 x1
__global__ __launch_bounds__(256)
void k_gather128(const __half* __restrict__ h, const float* __restrict__ b1,
                 __half* __restrict__ out, int M)
{
    int gid  = blockIdx.x * blockDim.x + threadIdx.x;
    int node = gid >> 4;
    int lane = gid & 15;
    if (node >= M) return;

    const int beg = g_off[node];
    const int end = g_off[node + 1];
    const uint4* h4 = (const uint4*)h;

    float2 a[4] = {{0.f,0.f},{0.f,0.f},{0.f,0.f},{0.f,0.f}};

    int j = beg;
    for (; j + 4 <= end; j += 4) {
        int s0 = g_esrc[j + 0], s1 = g_esrc[j + 1];
        int s2 = g_esrc[j + 2], s3 = g_esrc[j + 3];
        uint4 v0 = h4[(size_t)s0 * 16 + lane];
        uint4 v1 = h4[(size_t)s1 * 16 + lane];
        uint4 v2 = h4[(size_t)s2 * 16 + lane];
        uint4 v3 = h4[(size_t)s3 * 16 + lane];
        acc8(a, v0); acc8(a, v1); acc8(a, v2); acc8(a, v3);
    }
    for (; j < end; j++) {
        int s = g_esrc[j];
        acc8(a, h4[(size_t)s * 16 + lane]);
    }

    float nn = rsqrtf(fmaxf((float)(end - beg), 1.f));
    const float4* b4 = (const float4*)b1;
    float4 bb0 = b4[lane * 2 + 0];
    float4 bb1 = b4[lane * 2 + 1];
    float r0x = fmaxf(fmaf(a[0].x, nn, bb0.x), 0.f);
    float r0y = fmaxf(fmaf(a[0].y, nn, bb0.y), 0.f);
    float r0z = fmaxf(fmaf(a[1].x, nn, bb0.z), 0.f);
    float r0w = fmaxf(fmaf(a[1].y, nn, bb0.w), 0.f);
    float r1x = fmaxf(fmaf(a[2].x, nn, bb1.x), 0.f);
    float r1y = fmaxf(fmaf(a[2].y, nn, bb1.y), 0.f);
    float r1z = fmaxf(fmaf(a[3].x, nn, bb1.z), 0.f);
    float r1w = fmaxf(fmaf(a[3].y, nn, bb1.w), 0.f);
    uint4 o;
    o.x = h2_as_u32(__floats2half2_rn(r0x, r0y));
    o.y = h2_as_u32(__floats2half2_rn(r0z, r0w));
    o.z = h2_as_u32(__floats2half2_rn(r1x, r1y));
    o.w = h2_as_u32(__floats2half2_rn(r1z, r1w));
    ((uint4*)out)[(size_t)node * 16 + lane] = o;
}

// D=64: 8 lanes/node, 8 channels/lane. agg*inorm + b2 -> fp32 out
__global__ __launch_bounds__(256)
void k_gather64(const __half* __restrict__ h, const float* __restrict__ b2,
                float* __restrict__ out, int M)
{
    int gid  = blockIdx.x * blockDim.x + threadIdx.x;
    int node = gid >> 3;
    int sub  = gid & 7;
    if (node >= M) return;

    const int beg = g_off[node];
    const int end = g_off[node + 1];
    const uint4* h4 = (const uint4*)h;

    float2 a[4] = {{0.f,0.f},{0.f,0.f},{0.f,0.f},{0.f,0.f}};

    int j = beg;
    for (; j + 4 <= end; j += 4) {
        int s0 = g_esrc[j + 0], s1 = g_esrc[j + 1];
        int s2 = g_esrc[j + 2], s3 = g_esrc[j + 3];
        uint4 v0 = h4[(size_t)s0 * 8 + sub];
        uint4 v1 = h4[(size_t)s1 * 8 + sub];
        uint4 v2 = h4[(size_t)s2 * 8 + sub];
        uint4 v3 = h4[(size_t)s3 * 8 + sub];
        acc8(a, v0); acc8(a, v1); acc8(a, v2); acc8(a, v3);
    }
    for (; j < end; j++) {
        int s = g_esrc[j];
        acc8(a, h4[(size_t)s * 8 + sub]);
    }

    float nn = rsqrtf(fmaxf((float)(end - beg), 1.f));
    const float4* b4 = (const float4*)b2;
    float4 bb0 = b4[sub * 2 + 0];
    float4 bb1 = b4[sub * 2 + 1];
    float4 r0, r1;
    r0.x = fmaf(a[0].x, nn, bb0.x);
    r0.y = fmaf(a[0].y, nn, bb0.y);
    r0.z = fmaf(a[1].x, nn, bb0.z);
    r0.w = fmaf(a[1].y, nn, bb0.w);
    r1.x = fmaf(a[2].x, nn, bb1.x);
    r1.y = fmaf(a[2].y, nn, bb1.y);
    r1.z = fmaf(a[3].x, nn, bb1.z);
    r1.w = fmaf(a[3].y, nn, bb1.w);
    float4* o4 = (float4*)(out + (size_t)node * 64);
    o4[sub * 2 + 0] = r0;
    o4[sub * 2 + 1] = r1;
}

// ---------------- launch ----------------------------------------------------
extern "C" void kernel_launch(void* const* d_in, const int* in_sizes, int n_in,
                              void* d_out, int out_size)
{
    const float* feat = (const float*)d_in[0];
    const int*   src  = (const int*)  d_in[1];
    const int*   dst  = (const int*)  d_in[2];
    const float* W1   = (const float*)d_in[3];
    const float* b1   = (const float*)d_in[4];
    const float* W2   = (const float*)d_in[5];
    const float* b2   = (const float*)d_in[6];
    float* out = (float*)d_out;

    const int M  = in_sizes[0] / IN_DIM;   // 100000
    const int nE = in_sizes[1];            // 1600000

    float *pA = nullptr, *pB = nullptr;
    __half *w1h = nullptr, *w2h = nullptr;
    cudaGetSymbolAddress((void**)&pA, g_bufA);
    cudaGetSymbolAddress((void**)&pB, g_bufB);
    cudaGetSymbolAddress((void**)&w1h, g_W1h);
    cudaGetSymbolAddress((void**)&w2h, g_W2h);
    __half* hA  = (__half*)pA;             // fp16 message buffer (h1/h2)
    __half* x1h = (__half*)pB;             // fp16 x1

    constexpr int TSM1 = (128 * 136 + 128 * (128 + 8)) * 2 + 8 * 16 * 20 * 4; // 79872
    constexpr int TSM2 = (128 * 136 + 128 * (64 + 8)) * 2 + 8 * 16 * 20 * 4;  // 63488
    cudaFuncSetAttribute((const void*)k_tgemm<128, false>,
                         cudaFuncAttributeMaxDynamicSharedMemorySize, TSM1);
    cudaFuncSetAttribute((const void*)k_tgemm<64, true>,
                         cudaFuncAttributeMaxDynamicSharedMemorySize, TSM2);

    static cudaStream_t s_side = nullptr;
    static cudaEvent_t  s_evFork = nullptr, s_evJoin = nullptr;
    if (!s_side) {
        cudaStreamCreateWithFlags(&s_side, cudaStreamNonBlocking);
        cudaEventCreateWithFlags(&s_evFork, cudaEventDisableTiming);
        cudaEventCreateWithFlags(&s_evJoin, cudaEventDisableTiming);
    }

    const int nb = (M + 1023) >> 10;
    const int ng = (M + 127) / 128;
    const int n4 = (M + 3) / 4;

    // 0) prep: zero counts (int4) + weight fp16 converts
    k_prep<<<(n4 + 255) / 256, 256>>>(W1, W2, n4);
    cudaEventRecord(s_evFork, 0);

    // side stream: indeg count + CSR build (independent of gemm1)
    cudaStreamWaitEvent(s_side, s_evFork, 0);
    k_count_dst<<<(nE / 4 + 255) / 256, 256, 0, s_side>>>(dst, nE);
    k_scan1<<<nb, 1024, 0, s_side>>>(M);
    k_scan2<<<1, 256, 0, s_side>>>(nb);
    k_scan3<<<(M + 255) / 256, 256, 0, s_side>>>(M, nE);
    k_fill<<<(nE / 2 + 255) / 256, 256, 0, s_side>>>(src, dst, nE);
    cudaEventRecord(s_evJoin, s_side);

    // main stream: outdeg count + gemm1 (fp32 in, fp16 out)
    k_count_src<<<(nE / 4 + 255) / 256, 256>>>(src, nE);
    k_tgemm<128, false><<<ng, 256, TSM1>>>(feat, w1h, hA, M);

    // join: gather needs CSR + h1
    cudaStreamWaitEvent(0, s_evJoin, 0);
    k_gather128<<<((size_t)M * 16 + 255) / 256, 256>>>(hA, b1, x1h, M);

    // layer 2: gemm2 (fp16 in, fp16 out)
    k_tgemm<64, true><<<ng, 256, TSM2>>>(x1h, w2h, hA, M);
    k_gather64<<<((size_t)M * 8 + 255) / 256, 256>>>(hA, b2, out, M);
}